// round 11
// baseline (speedup 1.0000x reference)
#include <cuda_runtime.h>
#include <cuda_bf16.h>
#include <math.h>
#include <stdint.h>

#define BB     2
#define LL     4096
#define DMODEL 1024
#define DSTATE 64
#define DCONV  4
#define DINNER 2048
#define ROWS   (BB*LL)
#define EPSV   1.1920929e-07f
#define CHUNK  128
#define NCHUNK (LL/CHUNK)
#define LOG2E  1.44269504088896340736f

// ---------------- scratch ----------------
__device__ __align__(128) float g_xz [ROWS * (2*DINNER)];
__device__ __align__(128) float g_xc [ROWS * DINNER];
__device__ __align__(128) float g_bc [ROWS * 128];
__device__ __align__(128) float g_dt [ROWS * DINNER];
__device__ __align__(128) float g_y  [ROWS * DINNER];
__device__ __align__(128) float g_E  [BB*NCHUNK*DSTATE*DINNER];
__device__ __align__(128) float g_P  [BB*NCHUNK*DSTATE*DINNER];
__device__ __align__(128) float g_hin[BB*NCHUNK*DSTATE*DINNER];
__device__ __align__(128) __nv_bfloat16 g_xh  [ROWS*DMODEL], g_xl  [ROWS*DMODEL];
__device__ __align__(128) __nv_bfloat16 g_xch [ROWS*DINNER], g_xcl [ROWS*DINNER];
__device__ __align__(128) __nv_bfloat16 g_ynh [ROWS*DINNER], g_ynl [ROWS*DINNER];
// weights: transposed split [N][K]
__device__ __align__(128) __nv_bfloat16 g_winh [4096*1024], g_winl [4096*1024];
__device__ __align__(128) __nv_bfloat16 g_wxh  [128*2048],  g_wxl  [128*2048];   // B/C cols only
__device__ __align__(128) __nv_bfloat16 g_wdth [2048*2048], g_wdtl [2048*2048];  // W_dt^T [n][j]
__device__ __align__(128) __nv_bfloat16 g_wouth[1024*2048], g_woutl[1024*2048];
// direct split of Wx dt-columns: [k][j] = W_x[k][128+j]
__device__ __align__(128) __nv_bfloat16 g_wx2h [2048*2048], g_wx2l [2048*2048];
// combined weight Wc^T[n][k] = (Wx2 @ W_dt)^T, split
__device__ __align__(128) __nv_bfloat16 g_wch  [2048*2048], g_wcl  [2048*2048];

// ---------------- helpers ----------------
__device__ __forceinline__ float ex2f(float x){ float y; asm("ex2.approx.ftz.f32 %0, %1;":"=f"(y):"f"(x)); return y; }
__device__ __forceinline__ float softplus_f(float x){ return x > 20.f ? x : log1pf(expf(x)); }
__device__ __forceinline__ float silu_f(float x){ return x / (1.f + expf(-x)); }
__device__ __forceinline__ uint32_t pack_bf2(float lo, float hi){
    uint32_t r; asm("cvt.rn.bf16x2.f32 %0, %1, %2;":"=r"(r):"f"(hi),"f"(lo)); return r;
}
__device__ __forceinline__ uint32_t smem_u32(const void* p){
    uint32_t a; asm("{ .reg .u64 t; cvta.to.shared.u64 t, %1; cvt.u32.u64 %0, t; }":"=r"(a):"l"(p)); return a;
}
__device__ __forceinline__ void mma_bf16(float (&d)[4], const uint32_t* a, const uint32_t* b){
    asm volatile("mma.sync.aligned.m16n8k16.row.col.f32.bf16.bf16.f32 "
        "{%0,%1,%2,%3}, {%4,%5,%6,%7}, {%8,%9}, {%0,%1,%2,%3};"
        : "+f"(d[0]), "+f"(d[1]), "+f"(d[2]), "+f"(d[3])
        : "r"(a[0]), "r"(a[1]), "r"(a[2]), "r"(a[3]), "r"(b[0]), "r"(b[1]));
}
__device__ __forceinline__ void ldsm4(uint32_t* r, uint32_t addr){
    asm volatile("ldmatrix.sync.aligned.m8n8.x4.shared.b16 {%0,%1,%2,%3}, [%4];"
        : "=r"(r[0]), "=r"(r[1]), "=r"(r[2]), "=r"(r[3]) : "r"(addr));
}
__device__ __forceinline__ void cp16(uint32_t dst, const void* src){
    asm volatile("cp.async.cg.shared.global [%0], [%1], 16;" :: "r"(dst), "l"(src) : "memory");
}
__device__ __forceinline__ uint32_t swz(int row, int ch){
    return (uint32_t)(row*64 + ((ch ^ ((row>>1)&3))<<4));
}

// ---------------- HMMA bf16x3 core: 128 x NT tile, BK=32, 512 threads,
// 3-stage cp.async ring, one barrier per chunk.
template<int NT, int NG>   // NG = NT/128
__device__ __forceinline__ void gemm_core_v3(
    const __nv_bfloat16* __restrict__ Ah, const __nv_bfloat16* __restrict__ Al,
    const __nv_bfloat16* __restrict__ Bh, const __nv_bfloat16* __restrict__ Bl,
    int ktot, float (&acc)[4][2*NG][4])
{
    constexpr int STG = 16384 + NT*128;
    extern __shared__ __align__(128) char smbuf[];
    const uint32_t sm = smem_u32(smbuf);
    const int t    = threadIdx.x;
    const int lane = t & 31;
    const int wid  = t >> 5;
    const int m0   = (wid & 1) * 64;
    const int n0   = (wid >> 1) * (16*NG);
    const int lr   = lane & 15;
    const int lc   = lane >> 4;
    const int kch  = ktot >> 5;

    auto load_stage = [&](int c, int s){
        const uint32_t base = sm + (uint32_t)s * STG;
        const int kb = c * 32;
        {
            int row = t >> 2, ch = t & 3;
            uint32_t d = base + swz(row, ch);
            size_t so = (size_t)row * ktot + kb + ch*8;
            cp16(d, Ah + so);
            cp16(d + 8192, Al + so);
        }
        #pragma unroll
        for (int i = 0; i < NG; i++){
            int idx = i*512 + t;
            int row = idx >> 2, ch = idx & 3;
            uint32_t d = base + 16384 + swz(row, ch);
            size_t so = (size_t)row * ktot + kb + ch*8;
            cp16(d, Bh + so);
            cp16(d + NT*64, Bl + so);
        }
        asm volatile("cp.async.commit_group;":::"memory");
    };

    load_stage(0, 0);
    load_stage(1, 1);

    int s = 0, sl = 2;
    for (int c = 0; c < kch; c++){
        if (c + 1 < kch) asm volatile("cp.async.wait_group 1;":::"memory");
        else             asm volatile("cp.async.wait_group 0;":::"memory");
        __syncthreads();
        const uint32_t base = sm + (uint32_t)s * STG;
        #pragma unroll
        for (int ks = 0; ks < 2; ks++){
            const int ch = 2*ks + lc;
            uint32_t bh[NG][4], bl[NG][4];
            #pragma unroll
            for (int g = 0; g < NG; g++){
                int r = n0 + g*16 + lr;
                uint32_t a = base + 16384 + swz(r, ch);
                ldsm4(bh[g], a);
                ldsm4(bl[g], a + NT*64);
            }
            #pragma unroll
            for (int mt = 0; mt < 4; mt++){
                int r = m0 + mt*16 + lr;
                uint32_t a = base + swz(r, ch);
                uint32_t ah[4], al[4];
                ldsm4(ah, a);
                ldsm4(al, a + 8192);
                #pragma unroll
                for (int nt = 0; nt < 2*NG; nt++){
                    const int g = nt >> 1, sel = nt & 1;
                    uint32_t bfh[2] = { bh[g][sel], bh[g][sel+2] };
                    uint32_t bfl[2] = { bl[g][sel], bl[g][sel+2] };
                    mma_bf16(acc[mt][nt], ah, bfh);
                    mma_bf16(acc[mt][nt], al, bfh);
                    mma_bf16(acc[mt][nt], ah, bfl);
                }
            }
        }
        if (c + 2 < kch) load_stage(c + 2, sl);
        s  = (s  == 2) ? 0 : s  + 1;
        sl = (sl == 2) ? 0 : sl + 1;
    }
}

#define EPI3_SETUP(NT, NG) \
    const int lane = threadIdx.x & 31; \
    const int wid  = threadIdx.x >> 5; \
    const int mrow = blockIdx.y * 128 + (wid & 1) * 64 + (lane >> 2); \
    const int ncol = blockIdx.x * NT + (wid >> 1) * (16*NG) + (lane & 3) * 2;

// ---------------- GEMM kernels ----------------
__global__ __launch_bounds__(512, 1) void gemm1_tc(){  // xz = x @ W_in
    float acc[4][4][4] = {};
    gemm_core_v3<256,2>(g_xh + (size_t)blockIdx.y*128*DMODEL, g_xl + (size_t)blockIdx.y*128*DMODEL,
                        g_winh + (size_t)blockIdx.x*256*DMODEL, g_winl + (size_t)blockIdx.x*256*DMODEL,
                        DMODEL, acc);
    EPI3_SETUP(256, 2);
    #pragma unroll
    for (int mt = 0; mt < 4; mt++)
        #pragma unroll
        for (int nt = 0; nt < 4; nt++){
            int r = mrow + mt*16, cc = ncol + nt*8;
            *(float2*)&g_xz[(size_t)r*(2*DINNER) + cc]     = make_float2(acc[mt][nt][0], acc[mt][nt][1]);
            *(float2*)&g_xz[(size_t)(r+8)*(2*DINNER) + cc] = make_float2(acc[mt][nt][2], acc[mt][nt][3]);
        }
}
__global__ __launch_bounds__(512, 1) void gemm2a_tc(){ // bc = xc @ W_x[:,0:128]
    float acc[4][2][4] = {};
    gemm_core_v3<128,1>(g_xch + (size_t)blockIdx.y*128*DINNER, g_xcl + (size_t)blockIdx.y*128*DINNER,
                        g_wxh, g_wxl, DINNER, acc);
    EPI3_SETUP(128, 1);
    #pragma unroll
    for (int mt = 0; mt < 4; mt++)
        #pragma unroll
        for (int nt = 0; nt < 2; nt++){
            int r = mrow + mt*16, cc = ncol + nt*8;
            *(float2*)&g_bc[(size_t)r*128 + cc]     = make_float2(acc[mt][nt][0], acc[mt][nt][1]);
            *(float2*)&g_bc[(size_t)(r+8)*128 + cc] = make_float2(acc[mt][nt][2], acc[mt][nt][3]);
        }
}
// combine: Wc^T[n][k] = sum_j WdtT[n][j] * Wx2[k][j]   (2048x2048x2048)
__global__ __launch_bounds__(512, 1) void wcombine_tc(){
    float acc[4][4][4] = {};
    gemm_core_v3<256,2>(g_wdth + (size_t)blockIdx.y*128*2048, g_wdtl + (size_t)blockIdx.y*128*2048,
                        g_wx2h + (size_t)blockIdx.x*256*2048, g_wx2l + (size_t)blockIdx.x*256*2048,
                        2048, acc);
    EPI3_SETUP(256, 2);
    #pragma unroll
    for (int mt = 0; mt < 4; mt++)
        #pragma unroll
        for (int nt = 0; nt < 4; nt++){
            int r = mrow + mt*16, cc = ncol + nt*8;
            #pragma unroll
            for (int hrow = 0; hrow < 2; hrow++){
                float v0 = acc[mt][nt][2*hrow], v1 = acc[mt][nt][2*hrow+1];
                uint32_t hp = pack_bf2(v0, v1);
                uint32_t lp = pack_bf2(v0 - __uint_as_float(hp << 16),
                                       v1 - __uint_as_float(hp & 0xFFFF0000u));
                size_t o = (size_t)(r + 8*hrow)*2048 + cc;
                *(uint32_t*)&g_wch[o] = hp;
                *(uint32_t*)&g_wcl[o] = lp;
            }
        }
}
__global__ __launch_bounds__(512, 1) void gemm3_tc(const float* __restrict__ b_dt){ // dt = softplus(xc@Wc + b)
    float acc[4][4][4] = {};
    gemm_core_v3<256,2>(g_xch + (size_t)blockIdx.y*128*DINNER, g_xcl + (size_t)blockIdx.y*128*DINNER,
                        g_wch + (size_t)blockIdx.x*256*2048, g_wcl + (size_t)blockIdx.x*256*2048,
                        DINNER, acc);
    EPI3_SETUP(256, 2);
    #pragma unroll
    for (int mt = 0; mt < 4; mt++)
        #pragma unroll
        for (int nt = 0; nt < 4; nt++){
            int r = mrow + mt*16, cc = ncol + nt*8;
            float b0 = b_dt[cc], b1 = b_dt[cc+1];
            g_dt[(size_t)r*DINNER + cc]       = softplus_f(acc[mt][nt][0] + b0);
            g_dt[(size_t)r*DINNER + cc + 1]   = softplus_f(acc[mt][nt][1] + b1);
            g_dt[(size_t)(r+8)*DINNER + cc]   = softplus_f(acc[mt][nt][2] + b0);
            g_dt[(size_t)(r+8)*DINNER + cc+1] = softplus_f(acc[mt][nt][3] + b1);
        }
}
__global__ __launch_bounds__(512, 1) void gemm4_tc(float* __restrict__ out){
    float acc[4][4][4] = {};
    gemm_core_v3<256,2>(g_ynh + (size_t)blockIdx.y*128*DINNER, g_ynl + (size_t)blockIdx.y*128*DINNER,
                        g_wouth + (size_t)blockIdx.x*256*DINNER, g_woutl + (size_t)blockIdx.x*256*DINNER,
                        DINNER, acc);
    EPI3_SETUP(256, 2);
    #pragma unroll
    for (int mt = 0; mt < 4; mt++)
        #pragma unroll
        for (int nt = 0; nt < 4; nt++){
            int r = mrow + mt*16, cc = ncol + nt*8;
            *(float2*)&out[(size_t)r*DMODEL + cc]     = make_float2(acc[mt][nt][0], acc[mt][nt][1]);
            *(float2*)&out[(size_t)(r+8)*DMODEL + cc] = make_float2(acc[mt][nt][2], acc[mt][nt][3]);
        }
}

// ---------------- prep ----------------
__global__ __launch_bounds__(256) void split_x_kernel(const float* __restrict__ x){
    int idx = blockIdx.x*256 + threadIdx.x;
    float v = x[idx];
    __nv_bfloat16 h = __float2bfloat16(v);
    g_xh[idx] = h;
    g_xl[idx] = __float2bfloat16(v - __bfloat162float(h));
}
__global__ __launch_bounds__(256) void wsplit_kernel(const float* __restrict__ W,
                                                     __nv_bfloat16* __restrict__ oh,
                                                     __nv_bfloat16* __restrict__ ol,
                                                     int K, int N){
    __shared__ float tl[32][33];
    const int n0 = blockIdx.x*32, k0 = blockIdx.y*32;
    const int tx = threadIdx.x & 31, ty = threadIdx.x >> 5;
    #pragma unroll
    for (int i = 0; i < 4; i++)
        tl[ty + i*8][tx] = W[(size_t)(k0 + ty + i*8)*N + n0 + tx];
    __syncthreads();
    #pragma unroll
    for (int i = 0; i < 4; i++){
        int nl = ty + i*8;
        float v = tl[tx][nl];
        __nv_bfloat16 h = __float2bfloat16(v);
        size_t o = (size_t)(n0 + nl)*K + k0 + tx;
        oh[o] = h;
        ol[o] = __float2bfloat16(v - __bfloat162float(h));
    }
}
// direct (no transpose) split: out[k][j] = W[k][coloff + j], j-contiguous
__global__ __launch_bounds__(256) void wsplit_direct(const float* __restrict__ W,
                                                     __nv_bfloat16* __restrict__ oh,
                                                     __nv_bfloat16* __restrict__ ol,
                                                     int ldw, int coloff, int JCOLS){
    int idx = blockIdx.x*256 + threadIdx.x;
    int k = idx / JCOLS, j = idx - k*JCOLS;
    float v = W[(size_t)k*ldw + coloff + j];
    __nv_bfloat16 h = __float2bfloat16(v);
    oh[idx] = h;
    ol[idx] = __float2bfloat16(v - __bfloat162float(h));
}

// ---------------- conv + SiLU ----------------
__global__ __launch_bounds__(256) void conv_silu_kernel(const float* __restrict__ cw,
                                                        const float* __restrict__ cb){
    int idx = blockIdx.x*256 + threadIdx.x;
    int d   = idx & (DINNER - 1);
    int row = idx >> 11;
    int t   = row & (LL - 1);
    float acc = cb[d];
    #pragma unroll
    for (int k = 0; k < DCONV; k++){
        int tt = t - (DCONV - 1) + k;
        if (tt >= 0)
            acc = fmaf(g_xz[(size_t)(row - (DCONV - 1) + k)*(2*DINNER) + d], cw[d*DCONV + k], acc);
    }
    float v = silu_f(acc);
    g_xc[idx] = v;
    __nv_bfloat16 h = __float2bfloat16(v);
    g_xch[idx] = h;
    g_xcl[idx] = __float2bfloat16(v - __bfloat162float(h));
}

// ---------------- scan ----------------
__global__ __launch_bounds__(256) void scan_phase1(const float* __restrict__ A_log){
    const int blk = blockIdx.x;
    const int dgrp = blk & 15, chunk = (blk >> 4) & (NCHUNK-1), b = blk >> 9;
    const int tid = threadIdx.x, dloc = tid >> 1, half = tid & 1;
    const int d = dgrp*128 + dloc, s0 = half*32;
    const float u = -expf(A_log[d*DSTATE]) * LOG2E;
    float a2[32], h[32], p[32];
    bool fast = true;
    #pragma unroll
    for (int i = 0; i < 32; i++){
        a2[i] = -expf(A_log[d*DSTATE + s0 + i]) * LOG2E;
        float ex = u * (float)(s0 + i + 1);
        fast = fast && (fabsf(a2[i] - ex) <= 1e-6f*fabsf(ex) + 1e-30f);
        h[i] = 0.f; p[i] = 1.f;
    }
    __shared__ float sBC[2][128];
    const int rowbase = b*LL + chunk*CHUNK;
    for (int t = 0; t < CHUNK; t++){
        const int row = rowbase + t;
        if (tid < 128) sBC[t & 1][tid] = g_bc[(size_t)row*128 + tid];
        __syncthreads();
        const float dtv = g_dt[(size_t)row*DINNER + d];
        const float uv  = dtv * g_xc[(size_t)row*DINNER + d];
        const float* Bv = &sBC[t & 1][s0];
        if (fast){
            float q = ex2f(dtv * u), dA;
            if (s0 == 0) dA = q;
            else { float q2=q*q, q4=q2*q2, q8=q4*q4, q16=q8*q8, q32=q16*q16; dA = q32*q; }
            #pragma unroll
            for (int i = 0; i < 32; i++){
                p[i] *= dA;
                h[i] = fmaf(dA, h[i], uv * Bv[i]);
                dA *= q;
            }
        } else {
            #pragma unroll
            for (int i = 0; i < 32; i++){
                float dA = ex2f(dtv * a2[i]);
                p[i] *= dA;
                h[i] = fmaf(dA, h[i], uv * Bv[i]);
            }
        }
    }
    const int base = ((b*NCHUNK + chunk)*DSTATE + s0)*DINNER + d;
    #pragma unroll
    for (int i = 0; i < 32; i++){ g_E[base + i*DINNER] = h[i]; g_P[base + i*DINNER] = p[i]; }
}
__global__ __launch_bounds__(256) void scan_combine(){
    const int idx = blockIdx.x*256 + threadIdx.x;
    const int d = idx & (DINNER-1), bs = idx >> 11, b = bs >> 6, s = bs & 63;
    float h = 0.f;
    for (int j = 0; j < NCHUNK; j++){
        const int o = ((b*NCHUNK + j)*DSTATE + s)*DINNER + d;
        g_hin[o] = h;
        h = fmaf(g_P[o], h, g_E[o]);
    }
}
__global__ __launch_bounds__(256) void scan_phase3(const float* __restrict__ A_log,
                                                   const float* __restrict__ D_param){
    const int blk = blockIdx.x;
    const int dgrp = blk & 15, chunk = (blk >> 4) & (NCHUNK-1), b = blk >> 9;
    const int tid = threadIdx.x, dloc = tid >> 1, half = tid & 1;
    const int d = dgrp*128 + dloc, s0 = half*32;
    const float u = -expf(A_log[d*DSTATE]) * LOG2E;
    float a2[32], h[32];
    bool fast = true;
    const int hbase = ((b*NCHUNK + chunk)*DSTATE + s0)*DINNER + d;
    #pragma unroll
    for (int i = 0; i < 32; i++){
        a2[i] = -expf(A_log[d*DSTATE + s0 + i]) * LOG2E;
        float ex = u * (float)(s0 + i + 1);
        fast = fast && (fabsf(a2[i] - ex) <= 1e-6f*fabsf(ex) + 1e-30f);
        h[i]  = g_hin[hbase + i*DINNER];
    }
    const float Dv = D_param[d];
    __shared__ float sBC[2][128];
    const int rowbase = b*LL + chunk*CHUNK;
    for (int t = 0; t < CHUNK; t++){
        const int row = rowbase + t;
        if (tid < 128) sBC[t & 1][tid] = g_bc[(size_t)row*128 + tid];
        __syncthreads();
        const float dtv = g_dt[(size_t)row*DINNER + d];
        const float xcv = g_xc[(size_t)row*DINNER + d];
        const float uv  = dtv * xcv;
        const float* Bv = &sBC[t & 1][s0];
        const float* Cv = &sBC[t & 1][64 + s0];
        float yacc = 0.f;
        if (fast){
            float q = ex2f(dtv * u), dA;
            if (s0 == 0) dA = q;
            else { float q2=q*q, q4=q2*q2, q8=q4*q4, q16=q8*q8, q32=q16*q16; dA = q32*q; }
            #pragma unroll
            for (int i = 0; i < 32; i++){
                h[i] = fmaf(dA, h[i], uv * Bv[i]);
                yacc = fmaf(h[i], Cv[i], yacc);
                dA *= q;
            }
        } else {
            #pragma unroll
            for (int i = 0; i < 32; i++){
                float dA = ex2f(dtv * a2[i]);
                h[i] = fmaf(dA, h[i], uv * Bv[i]);
                yacc = fmaf(h[i], Cv[i], yacc);
            }
        }
        yacc += __shfl_xor_sync(0xffffffffu, yacc, 1);
        if (half == 0){
            const size_t o = (size_t)row*DINNER + d;
            g_y[o] = yacc + Dv * xcv;
        }
    }
}

// ---------------- RMSNorm + silu(z) gate -> split bf16 ----------------
__global__ __launch_bounds__(256) void norm_kernel(const float* __restrict__ norm_w){
    const int row = blockIdx.x, tid = threadIdx.x;
    const size_t base = (size_t)row*DINNER;
    float ss = 0.f;
    for (int i = tid; i < DINNER; i += 256){
        float v = g_y[base + i];
        ss = fmaf(v, v, ss);
    }
    #pragma unroll
    for (int o = 16; o; o >>= 1) ss += __shfl_xor_sync(0xffffffffu, ss, o);
    __shared__ float red[8];
    __shared__ float s_inv;
    if ((tid & 31) == 0) red[tid >> 5] = ss;
    __syncthreads();
    if (tid == 0){
        float t = 0.f;
        #pragma unroll
        for (int i = 0; i < 8; i++) t += red[i];
        s_inv = rsqrtf(t/(float)DINNER + EPSV);
    }
    __syncthreads();
    const float inv = s_inv;
    for (int i = tid; i < DINNER; i += 256){
        float v  = g_y[base + i]*inv*norm_w[i];
        float zv = g_xz[(size_t)row*(2*DINNER) + DINNER + i];
        float yv = v*silu_f(zv);
        __nv_bfloat16 h = __float2bfloat16(yv);
        g_ynh[base + i] = h;
        g_ynl[base + i] = __float2bfloat16(yv - __bfloat162float(h));
    }
}

// ---------------- launch ----------------
extern "C" void kernel_launch(void* const* d_in, const int* in_sizes, int n_in,
                              void* d_out, int out_size){
    const float* x      = (const float*)d_in[0];
    const float* W_in   = (const float*)d_in[1];
    const float* conv_w = (const float*)d_in[2];
    const float* conv_b = (const float*)d_in[3];
    const float* W_x    = (const float*)d_in[4];
    const float* W_dt   = (const float*)d_in[5];
    const float* b_dt   = (const float*)d_in[6];
    const float* A_log  = (const float*)d_in[7];
    const float* D_par  = (const float*)d_in[8];
    const float* W_out  = (const float*)d_in[9];
    const float* norm_w = (const float*)d_in[10];
    float* out = (float*)d_out;

    const int SM256 = 3 * (16384 + 256*128);   // 147456
    const int SM128 = 3 * (16384 + 128*128);   // 98304
    cudaFuncSetAttribute(gemm1_tc,   cudaFuncAttributeMaxDynamicSharedMemorySize, SM256);
    cudaFuncSetAttribute(gemm2a_tc,  cudaFuncAttributeMaxDynamicSharedMemorySize, SM128);
    cudaFuncSetAttribute(wcombine_tc,cudaFuncAttributeMaxDynamicSharedMemorySize, SM256);
    cudaFuncSetAttribute(gemm3_tc,   cudaFuncAttributeMaxDynamicSharedMemorySize, SM256);
    cudaFuncSetAttribute(gemm4_tc,   cudaFuncAttributeMaxDynamicSharedMemorySize, SM256);

    __nv_bfloat16 *winh, *winl, *wxh, *wxl, *wdth, *wdtl, *wouth, *woutl, *wx2h, *wx2l;
    cudaGetSymbolAddress((void**)&winh, g_winh);  cudaGetSymbolAddress((void**)&winl, g_winl);
    cudaGetSymbolAddress((void**)&wxh,  g_wxh);   cudaGetSymbolAddress((void**)&wxl,  g_wxl);
    cudaGetSymbolAddress((void**)&wdth, g_wdth);  cudaGetSymbolAddress((void**)&wdtl, g_wdtl);
    cudaGetSymbolAddress((void**)&wouth,g_wouth); cudaGetSymbolAddress((void**)&woutl,g_woutl);
    cudaGetSymbolAddress((void**)&wx2h, g_wx2h);  cudaGetSymbolAddress((void**)&wx2l, g_wx2l);

    split_x_kernel<<<(ROWS*DMODEL)/256, 256>>>(x);
    wsplit_kernel<<<dim3(4096/32, 1024/32), 256>>>(W_in,  winh,  winl,  1024, 4096);
    wsplit_kernel<<<dim3(128/32,  2048/32), 256>>>(W_x,   wxh,   wxl,   2048, 2176);
    wsplit_kernel<<<dim3(2048/32, 2048/32), 256>>>(W_dt,  wdth,  wdtl,  2048, 2048);
    wsplit_kernel<<<dim3(1024/32, 2048/32), 256>>>(W_out, wouth, woutl, 2048, 1024);
    wsplit_direct<<<(2048*2048)/256, 256>>>(W_x, wx2h, wx2l, 2176, 128, 2048);

    wcombine_tc<<<dim3(8, 16), 512, SM256>>>();          // Wc = Wx2 @ W_dt (17 GF)
    gemm1_tc<<<dim3(16, 64), 512, SM256>>>();
    conv_silu_kernel<<<(ROWS*DINNER)/256, 256>>>(conv_w, conv_b);
    gemm2a_tc<<<dim3(1, 64), 512, SM128>>>();
    gemm3_tc<<<dim3(8, 64), 512, SM256>>>(b_dt);         // dt = softplus(xc@Wc + b)
    scan_phase1<<<BB*NCHUNK*(DINNER/128), 256>>>(A_log);
    scan_combine<<<(BB*DSTATE*DINNER)/256, 256>>>();
    scan_phase3<<<BB*NCHUNK*(DINNER/128), 256>>>(A_log, D_par);
    norm_kernel<<<ROWS, 256>>>(norm_w);
    gemm4_tc<<<dim3(4, 64), 512, SM256>>>(out);
}

// round 13
// speedup vs baseline: 1.0404x; 1.0404x over previous
#include <cuda_runtime.h>
#include <cuda.h>
#include <cuda_bf16.h>
#include <math.h>
#include <stdint.h>
#include <dlfcn.h>

#define BB     2
#define LL     4096
#define DMODEL 1024
#define DSTATE 64
#define DCONV  4
#define DINNER 2048
#define ROWS   (BB*LL)
#define EPSV   1.1920929e-07f
#define CHUNK  128
#define NCHUNK (LL/CHUNK)
#define LOG2E  1.44269504088896340736f

// ---------------- scratch ----------------
__device__ __align__(128) float g_xz [ROWS * (2*DINNER)];
__device__ __align__(128) float g_xc [ROWS * DINNER];
__device__ __align__(128) float g_bc [ROWS * 128];
__device__ __align__(128) float g_dt [ROWS * DINNER];
__device__ __align__(128) float g_y  [ROWS * DINNER];
__device__ __align__(128) float g_E  [BB*NCHUNK*DSTATE*DINNER];
__device__ __align__(128) float g_P  [BB*NCHUNK*DSTATE*DINNER];
__device__ __align__(128) float g_hin[BB*NCHUNK*DSTATE*DINNER];
__device__ __align__(128) __nv_bfloat16 g_xh  [ROWS*DMODEL], g_xl  [ROWS*DMODEL];
__device__ __align__(128) __nv_bfloat16 g_xch [ROWS*DINNER], g_xcl [ROWS*DINNER];
__device__ __align__(128) __nv_bfloat16 g_ynh [ROWS*DINNER], g_ynl [ROWS*DINNER];
__device__ __align__(128) __nv_bfloat16 g_winh [4096*1024], g_winl [4096*1024];
__device__ __align__(128) __nv_bfloat16 g_wxh  [128*2048],  g_wxl  [128*2048];
__device__ __align__(128) __nv_bfloat16 g_wdth [2048*2048], g_wdtl [2048*2048];
__device__ __align__(128) __nv_bfloat16 g_wouth[1024*2048], g_woutl[1024*2048];
__device__ __align__(128) __nv_bfloat16 g_wx2h [2048*2048], g_wx2l [2048*2048];
__device__ __align__(128) __nv_bfloat16 g_wch  [2048*2048], g_wcl  [2048*2048];

// ---------------- device helpers ----------------
__device__ __forceinline__ float ex2f(float x){ float y; asm("ex2.approx.ftz.f32 %0, %1;":"=f"(y):"f"(x)); return y; }
__device__ __forceinline__ float softplus_f(float x){ return x > 20.f ? x : log1pf(expf(x)); }
__device__ __forceinline__ float silu_f(float x){ return x / (1.f + expf(-x)); }
__device__ __forceinline__ uint32_t pack_bf2(float lo, float hi){
    uint32_t r; asm("cvt.rn.bf16x2.f32 %0, %1, %2;":"=r"(r):"f"(hi),"f"(lo)); return r;
}
__device__ __forceinline__ uint32_t smem_u32(const void* p){
    uint32_t a; asm("{ .reg .u64 t; cvta.to.shared.u64 t, %1; cvt.u32.u64 %0, t; }":"=r"(a):"l"(p)); return a;
}
__device__ __forceinline__ void mma_bf16(float (&d)[4], const uint32_t* a, const uint32_t* b){
    asm volatile("mma.sync.aligned.m16n8k16.row.col.f32.bf16.bf16.f32 "
        "{%0,%1,%2,%3}, {%4,%5,%6,%7}, {%8,%9}, {%0,%1,%2,%3};"
        : "+f"(d[0]), "+f"(d[1]), "+f"(d[2]), "+f"(d[3])
        : "r"(a[0]), "r"(a[1]), "r"(a[2]), "r"(a[3]), "r"(b[0]), "r"(b[1]));
}
__device__ __forceinline__ void ldsm4(uint32_t* r, uint32_t addr){
    asm volatile("ldmatrix.sync.aligned.m8n8.x4.shared.b16 {%0,%1,%2,%3}, [%4];"
        : "=r"(r[0]), "=r"(r[1]), "=r"(r[2]), "=r"(r[3]) : "r"(addr));
}
__device__ __forceinline__ void mbar_init(uint32_t a, uint32_t c){
    asm volatile("mbarrier.init.shared.b64 [%0], %1;"::"r"(a),"r"(c):"memory");
}
__device__ __forceinline__ void mbar_wait(uint32_t a, uint32_t par){
    asm volatile("{\n\t.reg .pred P;\n\tW_%=:\n\t"
        "mbarrier.try_wait.parity.acquire.cta.shared::cta.b64 P, [%0], %1, 0x989680;\n\t"
        "@P bra.uni D_%=;\n\tbra.uni W_%=;\n\tD_%=:\n\t}"::"r"(a),"r"(par):"memory");
}
__device__ __forceinline__ void tma2d(uint32_t smem, const CUtensorMap* m, int x, int y, uint32_t mb){
    asm volatile("cp.async.bulk.tensor.2d.shared::cta.global.tile.mbarrier::complete_tx::bytes "
        "[%0], [%1, {%2, %3}], [%4];" :: "r"(smem), "l"(m), "r"(x), "r"(y), "r"(mb) : "memory");
}
__device__ __forceinline__ uint32_t swz128(uint32_t off){ return off ^ ((off >> 3) & 0x70); }

// ---------------- TMA-fed HMMA bf16x3 core: 128 x NT tile, BK=64, 512 thr,
// 2-stage mbarrier pipeline. Stage: Ah@0(16K) Al@16K Bh@32K(NT*128) Bl after.
template<int NT, int NG>   // NG = NT/128
__device__ __forceinline__ void gemm_core_v4(
    const CUtensorMap* tAh, const CUtensorMap* tAl,
    const CUtensorMap* tBh, const CUtensorMap* tBl,
    int rowA, int rowB, int ktot, float (&acc)[4][2*NG][4])
{
    constexpr int STG = 32768 + NT*256;
    extern __shared__ __align__(1024) char smbuf[];
    const uint32_t sm  = (smem_u32(smbuf) + 1023u) & ~1023u;
    const uint32_t mb0 = sm + 2u*STG;
    const int t = threadIdx.x, lane = t & 31, wid = t >> 5;
    const int m0 = (wid & 1)*64, n0 = (wid >> 1)*(16*NG);
    const int lr = lane & 15, lc = lane >> 4;
    const int kch = ktot >> 6;

    if (t == 0){ mbar_init(mb0, 1); mbar_init(mb0 + 8, 1); }
    __syncthreads();

    auto issue = [&](int c, int s){
        if (t == 0){
            const uint32_t mb = mb0 + (uint32_t)s*8u;
            asm volatile("mbarrier.arrive.expect_tx.shared.b64 _, [%0], %1;"
                         :: "r"(mb), "r"((uint32_t)STG) : "memory");
            const uint32_t base = sm + (uint32_t)s*STG;
            const int kx = c*64;
            tma2d(base,                  tAh, kx, rowA, mb);
            tma2d(base + 16384,          tAl, kx, rowA, mb);
            tma2d(base + 32768,          tBh, kx, rowB, mb);
            tma2d(base + 32768 + NT*128, tBl, kx, rowB, mb);
        }
    };
    issue(0, 0);
    issue(1, 1);
    uint32_t ph[2] = {0u, 0u};

    for (int c = 0; c < kch; c++){
        const int s = c & 1;
        mbar_wait(mb0 + (uint32_t)s*8u, ph[s]); ph[s] ^= 1u;
        const uint32_t base = sm + (uint32_t)s*STG;
        #pragma unroll
        for (int ks = 0; ks < 4; ks++){
            const int ch = ks*2 + lc;
            uint32_t bh[NG][4], bl[NG][4];
            #pragma unroll
            for (int g = 0; g < NG; g++){
                uint32_t a = base + 32768 + swz128((uint32_t)((n0 + g*16 + lr)*128 + ch*16));
                ldsm4(bh[g], a);
                ldsm4(bl[g], a + NT*128);
            }
            #pragma unroll
            for (int mt = 0; mt < 4; mt++){
                uint32_t a = base + swz128((uint32_t)((m0 + mt*16 + lr)*128 + ch*16));
                uint32_t ah[4], al[4];
                ldsm4(ah, a);
                ldsm4(al, a + 16384);
                #pragma unroll
                for (int nt = 0; nt < 2*NG; nt++){
                    const int g = nt >> 1, sel = nt & 1;
                    uint32_t bfh[2] = { bh[g][sel], bh[g][sel+2] };
                    uint32_t bfl[2] = { bl[g][sel], bl[g][sel+2] };
                    mma_bf16(acc[mt][nt], ah, bfh);
                    mma_bf16(acc[mt][nt], al, bfh);
                    mma_bf16(acc[mt][nt], ah, bfl);
                }
            }
        }
        __syncthreads();              // all reads of stage s done
        if (c + 2 < kch) issue(c + 2, s);
    }
}

#define EPI3_SETUP(NT, NG) \
    const int lane = threadIdx.x & 31; \
    const int wid  = threadIdx.x >> 5; \
    const int mrow = blockIdx.y * 128 + (wid & 1) * 64 + (lane >> 2); \
    const int ncol = blockIdx.x * NT + (wid >> 1) * (16*NG) + (lane & 3) * 2;

// ---------------- GEMM kernels ----------------
__global__ __launch_bounds__(512, 1) void gemm1_tc(
    const __grid_constant__ CUtensorMap tAh, const __grid_constant__ CUtensorMap tAl,
    const __grid_constant__ CUtensorMap tBh, const __grid_constant__ CUtensorMap tBl){
    float acc[4][4][4] = {};
    gemm_core_v4<256,2>(&tAh,&tAl,&tBh,&tBl, blockIdx.y*128, blockIdx.x*256, DMODEL, acc);
    EPI3_SETUP(256, 2);
    #pragma unroll
    for (int mt = 0; mt < 4; mt++)
        #pragma unroll
        for (int nt = 0; nt < 4; nt++){
            int r = mrow + mt*16, cc = ncol + nt*8;
            *(float2*)&g_xz[(size_t)r*(2*DINNER) + cc]     = make_float2(acc[mt][nt][0], acc[mt][nt][1]);
            *(float2*)&g_xz[(size_t)(r+8)*(2*DINNER) + cc] = make_float2(acc[mt][nt][2], acc[mt][nt][3]);
        }
}
__global__ __launch_bounds__(512, 1) void gemm2a_tc(
    const __grid_constant__ CUtensorMap tAh, const __grid_constant__ CUtensorMap tAl,
    const __grid_constant__ CUtensorMap tBh, const __grid_constant__ CUtensorMap tBl){
    float acc[4][2][4] = {};
    gemm_core_v4<128,1>(&tAh,&tAl,&tBh,&tBl, blockIdx.y*128, 0, DINNER, acc);
    EPI3_SETUP(128, 1);
    #pragma unroll
    for (int mt = 0; mt < 4; mt++)
        #pragma unroll
        for (int nt = 0; nt < 2; nt++){
            int r = mrow + mt*16, cc = ncol + nt*8;
            *(float2*)&g_bc[(size_t)r*128 + cc]     = make_float2(acc[mt][nt][0], acc[mt][nt][1]);
            *(float2*)&g_bc[(size_t)(r+8)*128 + cc] = make_float2(acc[mt][nt][2], acc[mt][nt][3]);
        }
}
__global__ __launch_bounds__(512, 1) void wcombine_tc(
    const __grid_constant__ CUtensorMap tAh, const __grid_constant__ CUtensorMap tAl,
    const __grid_constant__ CUtensorMap tBh, const __grid_constant__ CUtensorMap tBl){
    float acc[4][4][4] = {};
    gemm_core_v4<256,2>(&tAh,&tAl,&tBh,&tBl, blockIdx.y*128, blockIdx.x*256, 2048, acc);
    EPI3_SETUP(256, 2);
    #pragma unroll
    for (int mt = 0; mt < 4; mt++)
        #pragma unroll
        for (int nt = 0; nt < 4; nt++){
            int r = mrow + mt*16, cc = ncol + nt*8;
            #pragma unroll
            for (int hrow = 0; hrow < 2; hrow++){
                float v0 = acc[mt][nt][2*hrow], v1 = acc[mt][nt][2*hrow+1];
                uint32_t hp = pack_bf2(v0, v1);
                uint32_t lp = pack_bf2(v0 - __uint_as_float(hp << 16),
                                       v1 - __uint_as_float(hp & 0xFFFF0000u));
                size_t o = (size_t)(r + 8*hrow)*2048 + cc;
                *(uint32_t*)&g_wch[o] = hp;
                *(uint32_t*)&g_wcl[o] = lp;
            }
        }
}
__global__ __launch_bounds__(512, 1) void gemm3_tc(
    const __grid_constant__ CUtensorMap tAh, const __grid_constant__ CUtensorMap tAl,
    const __grid_constant__ CUtensorMap tBh, const __grid_constant__ CUtensorMap tBl,
    const float* __restrict__ b_dt){
    float acc[4][4][4] = {};
    gemm_core_v4<256,2>(&tAh,&tAl,&tBh,&tBl, blockIdx.y*128, blockIdx.x*256, DINNER, acc);
    EPI3_SETUP(256, 2);
    #pragma unroll
    for (int mt = 0; mt < 4; mt++)
        #pragma unroll
        for (int nt = 0; nt < 4; nt++){
            int r = mrow + mt*16, cc = ncol + nt*8;
            float b0 = b_dt[cc], b1 = b_dt[cc+1];
            g_dt[(size_t)r*DINNER + cc]       = softplus_f(acc[mt][nt][0] + b0);
            g_dt[(size_t)r*DINNER + cc + 1]   = softplus_f(acc[mt][nt][1] + b1);
            g_dt[(size_t)(r+8)*DINNER + cc]   = softplus_f(acc[mt][nt][2] + b0);
            g_dt[(size_t)(r+8)*DINNER + cc+1] = softplus_f(acc[mt][nt][3] + b1);
        }
}
__global__ __launch_bounds__(512, 1) void gemm4_tc(
    const __grid_constant__ CUtensorMap tAh, const __grid_constant__ CUtensorMap tAl,
    const __grid_constant__ CUtensorMap tBh, const __grid_constant__ CUtensorMap tBl,
    float* __restrict__ out){
    float acc[4][4][4] = {};
    gemm_core_v4<256,2>(&tAh,&tAl,&tBh,&tBl, blockIdx.y*128, blockIdx.x*256, DINNER, acc);
    EPI3_SETUP(256, 2);
    #pragma unroll
    for (int mt = 0; mt < 4; mt++)
        #pragma unroll
        for (int nt = 0; nt < 4; nt++){
            int r = mrow + mt*16, cc = ncol + nt*8;
            *(float2*)&out[(size_t)r*DMODEL + cc]     = make_float2(acc[mt][nt][0], acc[mt][nt][1]);
            *(float2*)&out[(size_t)(r+8)*DMODEL + cc] = make_float2(acc[mt][nt][2], acc[mt][nt][3]);
        }
}

// ---------------- prep ----------------
__global__ __launch_bounds__(256) void split_x_kernel(const float* __restrict__ x){
    int idx = blockIdx.x*256 + threadIdx.x;
    float v = x[idx];
    __nv_bfloat16 h = __float2bfloat16(v);
    g_xh[idx] = h;
    g_xl[idx] = __float2bfloat16(v - __bfloat162float(h));
}
__global__ __launch_bounds__(256) void wsplit_kernel(const float* __restrict__ W,
                                                     __nv_bfloat16* __restrict__ oh,
                                                     __nv_bfloat16* __restrict__ ol,
                                                     int K, int N){
    __shared__ float tl[32][33];
    const int n0 = blockIdx.x*32, k0 = blockIdx.y*32;
    const int tx = threadIdx.x & 31, ty = threadIdx.x >> 5;
    #pragma unroll
    for (int i = 0; i < 4; i++)
        tl[ty + i*8][tx] = W[(size_t)(k0 + ty + i*8)*N + n0 + tx];
    __syncthreads();
    #pragma unroll
    for (int i = 0; i < 4; i++){
        int nl = ty + i*8;
        float v = tl[tx][nl];
        __nv_bfloat16 h = __float2bfloat16(v);
        size_t o = (size_t)(n0 + nl)*K + k0 + tx;
        oh[o] = h;
        ol[o] = __float2bfloat16(v - __bfloat162float(h));
    }
}
__global__ __launch_bounds__(256) void wsplit_direct(const float* __restrict__ W,
                                                     __nv_bfloat16* __restrict__ oh,
                                                     __nv_bfloat16* __restrict__ ol,
                                                     int ldw, int coloff, int JCOLS){
    int idx = blockIdx.x*256 + threadIdx.x;
    int k = idx / JCOLS, j = idx - k*JCOLS;
    float v = W[(size_t)k*ldw + coloff + j];
    __nv_bfloat16 h = __float2bfloat16(v);
    oh[idx] = h;
    ol[idx] = __float2bfloat16(v - __bfloat162float(h));
}

// ---------------- conv + SiLU ----------------
__global__ __launch_bounds__(256) void conv_silu_kernel(const float* __restrict__ cw,
                                                        const float* __restrict__ cb){
    int idx = blockIdx.x*256 + threadIdx.x;
    int d   = idx & (DINNER - 1);
    int row = idx >> 11;
    int t   = row & (LL - 1);
    float acc = cb[d];
    #pragma unroll
    for (int k = 0; k < DCONV; k++){
        int tt = t - (DCONV - 1) + k;
        if (tt >= 0)
            acc = fmaf(g_xz[(size_t)(row - (DCONV - 1) + k)*(2*DINNER) + d], cw[d*DCONV + k], acc);
    }
    float v = silu_f(acc);
    g_xc[idx] = v;
    __nv_bfloat16 h = __float2bfloat16(v);
    g_xch[idx] = h;
    g_xcl[idx] = __float2bfloat16(v - __bfloat162float(h));
}

// ---------------- scan ----------------
__global__ __launch_bounds__(256) void scan_phase1(const float* __restrict__ A_log){
    const int blk = blockIdx.x;
    const int dgrp = blk & 15, chunk = (blk >> 4) & (NCHUNK-1), b = blk >> 9;
    const int tid = threadIdx.x, dloc = tid >> 1, half = tid & 1;
    const int d = dgrp*128 + dloc, s0 = half*32;
    const float u = -expf(A_log[d*DSTATE]) * LOG2E;
    float a2[32], h[32], p[32];
    bool fast = true;
    #pragma unroll
    for (int i = 0; i < 32; i++){
        a2[i] = -expf(A_log[d*DSTATE + s0 + i]) * LOG2E;
        float ex = u * (float)(s0 + i + 1);
        fast = fast && (fabsf(a2[i] - ex) <= 1e-6f*fabsf(ex) + 1e-30f);
        h[i] = 0.f; p[i] = 1.f;
    }
    __shared__ float sBC[2][128];
    const int rowbase = b*LL + chunk*CHUNK;
    for (int t = 0; t < CHUNK; t++){
        const int row = rowbase + t;
        if (tid < 128) sBC[t & 1][tid] = g_bc[(size_t)row*128 + tid];
        __syncthreads();
        const float dtv = g_dt[(size_t)row*DINNER + d];
        const float uv  = dtv * g_xc[(size_t)row*DINNER + d];
        const float* Bv = &sBC[t & 1][s0];
        if (fast){
            float q = ex2f(dtv * u), dA;
            if (s0 == 0) dA = q;
            else { float q2=q*q, q4=q2*q2, q8=q4*q4, q16=q8*q8, q32=q16*q16; dA = q32*q; }
            #pragma unroll
            for (int i = 0; i < 32; i++){
                p[i] *= dA;
                h[i] = fmaf(dA, h[i], uv * Bv[i]);
                dA *= q;
            }
        } else {
            #pragma unroll
            for (int i = 0; i < 32; i++){
                float dA = ex2f(dtv * a2[i]);
                p[i] *= dA;
                h[i] = fmaf(dA, h[i], uv * Bv[i]);
            }
        }
    }
    const int base = ((b*NCHUNK + chunk)*DSTATE + s0)*DINNER + d;
    #pragma unroll
    for (int i = 0; i < 32; i++){ g_E[base + i*DINNER] = h[i]; g_P[base + i*DINNER] = p[i]; }
}
__global__ __launch_bounds__(256) void scan_combine(){
    const int idx = blockIdx.x*256 + threadIdx.x;
    const int d = idx & (DINNER-1), bs = idx >> 11, b = bs >> 6, s = bs & 63;
    float h = 0.f;
    for (int j = 0; j < NCHUNK; j++){
        const int o = ((b*NCHUNK + j)*DSTATE + s)*DINNER + d;
        g_hin[o] = h;
        h = fmaf(g_P[o], h, g_E[o]);
    }
}
__global__ __launch_bounds__(256) void scan_phase3(const float* __restrict__ A_log,
                                                   const float* __restrict__ D_param){
    const int blk = blockIdx.x;
    const int dgrp = blk & 15, chunk = (blk >> 4) & (NCHUNK-1), b = blk >> 9;
    const int tid = threadIdx.x, dloc = tid >> 1, half = tid & 1;
    const int d = dgrp*128 + dloc, s0 = half*32;
    const float u = -expf(A_log[d*DSTATE]) * LOG2E;
    float a2[32], h[32];
    bool fast = true;
    const int hbase = ((b*NCHUNK + chunk)*DSTATE + s0)*DINNER + d;
    #pragma unroll
    for (int i = 0; i < 32; i++){
        a2[i] = -expf(A_log[d*DSTATE + s0 + i]) * LOG2E;
        float ex = u * (float)(s0 + i + 1);
        fast = fast && (fabsf(a2[i] - ex) <= 1e-6f*fabsf(ex) + 1e-30f);
        h[i]  = g_hin[hbase + i*DINNER];
    }
    const float Dv = D_param[d];
    __shared__ float sBC[2][128];
    const int rowbase = b*LL + chunk*CHUNK;
    for (int t = 0; t < CHUNK; t++){
        const int row = rowbase + t;
        if (tid < 128) sBC[t & 1][tid] = g_bc[(size_t)row*128 + tid];
        __syncthreads();
        const float dtv = g_dt[(size_t)row*DINNER + d];
        const float xcv = g_xc[(size_t)row*DINNER + d];
        const float uv  = dtv * xcv;
        const float* Bv = &sBC[t & 1][s0];
        const float* Cv = &sBC[t & 1][64 + s0];
        float yacc = 0.f;
        if (fast){
            float q = ex2f(dtv * u), dA;
            if (s0 == 0) dA = q;
            else { float q2=q*q, q4=q2*q2, q8=q4*q4, q16=q8*q8, q32=q16*q16; dA = q32*q; }
            #pragma unroll
            for (int i = 0; i < 32; i++){
                h[i] = fmaf(dA, h[i], uv * Bv[i]);
                yacc = fmaf(h[i], Cv[i], yacc);
                dA *= q;
            }
        } else {
            #pragma unroll
            for (int i = 0; i < 32; i++){
                float dA = ex2f(dtv * a2[i]);
                h[i] = fmaf(dA, h[i], uv * Bv[i]);
                yacc = fmaf(h[i], Cv[i], yacc);
            }
        }
        yacc += __shfl_xor_sync(0xffffffffu, yacc, 1);
        if (half == 0){
            const size_t o = (size_t)row*DINNER + d;
            g_y[o] = yacc + Dv * xcv;
        }
    }
}

// ---------------- RMSNorm + silu(z) gate -> split bf16 ----------------
__global__ __launch_bounds__(256) void norm_kernel(const float* __restrict__ norm_w){
    const int row = blockIdx.x, tid = threadIdx.x;
    const size_t base = (size_t)row*DINNER;
    float ss = 0.f;
    for (int i = tid; i < DINNER; i += 256){
        float v = g_y[base + i];
        ss = fmaf(v, v, ss);
    }
    #pragma unroll
    for (int o = 16; o; o >>= 1) ss += __shfl_xor_sync(0xffffffffu, ss, o);
    __shared__ float red[8];
    __shared__ float s_inv;
    if ((tid & 31) == 0) red[tid >> 5] = ss;
    __syncthreads();
    if (tid == 0){
        float t = 0.f;
        #pragma unroll
        for (int i = 0; i < 8; i++) t += red[i];
        s_inv = rsqrtf(t/(float)DINNER + EPSV);
    }
    __syncthreads();
    const float inv = s_inv;
    for (int i = tid; i < DINNER; i += 256){
        float v  = g_y[base + i]*inv*norm_w[i];
        float zv = g_xz[(size_t)row*(2*DINNER) + DINNER + i];
        float yv = v*silu_f(zv);
        __nv_bfloat16 h = __float2bfloat16(yv);
        g_ynh[base + i] = h;
        g_ynl[base + i] = __float2bfloat16(yv - __bfloat162float(h));
    }
}

// ---------------- host-side tensormap builder (dlopen, no -lcuda) ----------
typedef CUresult (*EncFn)(CUtensorMap*, CUtensorMapDataType, cuuint32_t, void*,
    const cuuint64_t*, const cuuint64_t*, const cuuint32_t*, const cuuint32_t*,
    CUtensorMapInterleave, CUtensorMapSwizzle, CUtensorMapL2promotion, CUtensorMapFloatOOBfill);

static EncFn get_enc(){
    void* h = dlopen("libcuda.so.1", RTLD_LAZY | RTLD_GLOBAL);
    if (!h) h = dlopen("libcuda.so", RTLD_LAZY | RTLD_GLOBAL);
    if (!h) return nullptr;
    return (EncFn)dlsym(h, "cuTensorMapEncodeTiled");
}
static void mkmap(EncFn f, CUtensorMap* m, void* p, uint64_t K, uint64_t R, uint32_t boxR){
    if (!f || !p) return;   // degrade to wrong-answer, never segfault the harness
    cuuint64_t gd[2] = {K, R};
    cuuint64_t gs[1] = {K*2};
    cuuint32_t bd[2] = {64, boxR};
    cuuint32_t es[2] = {1, 1};
    f(m, CU_TENSOR_MAP_DATA_TYPE_BFLOAT16, 2, p, gd, gs, bd, es,
      CU_TENSOR_MAP_INTERLEAVE_NONE, CU_TENSOR_MAP_SWIZZLE_128B,
      CU_TENSOR_MAP_L2_PROMOTION_L2_128B, CU_TENSOR_MAP_FLOAT_OOB_FILL_NONE);
}

// ---------------- launch ----------------
extern "C" void kernel_launch(void* const* d_in, const int* in_sizes, int n_in,
                              void* d_out, int out_size){
    const float* x      = (const float*)d_in[0];
    const float* W_in   = (const float*)d_in[1];
    const float* conv_w = (const float*)d_in[2];
    const float* conv_b = (const float*)d_in[3];
    const float* W_x    = (const float*)d_in[4];
    const float* W_dt   = (const float*)d_in[5];
    const float* b_dt   = (const float*)d_in[6];
    const float* A_log  = (const float*)d_in[7];
    const float* D_par  = (const float*)d_in[8];
    const float* W_out  = (const float*)d_in[9];
    const float* norm_w = (const float*)d_in[10];
    float* out = (float*)d_out;

    const int STG256 = 32768 + 256*256;            // 98304
    const int STG128 = 32768 + 128*256;            // 65536
    const int SM256  = 2*STG256 + 1024 + 64;       // 197,696
    const int SM128  = 2*STG128 + 1024 + 64;       // 132,160
    cudaFuncSetAttribute(gemm1_tc,   cudaFuncAttributeMaxDynamicSharedMemorySize, SM256);
    cudaFuncSetAttribute(gemm2a_tc,  cudaFuncAttributeMaxDynamicSharedMemorySize, SM128);
    cudaFuncSetAttribute(wcombine_tc,cudaFuncAttributeMaxDynamicSharedMemorySize, SM256);
    cudaFuncSetAttribute(gemm3_tc,   cudaFuncAttributeMaxDynamicSharedMemorySize, SM256);
    cudaFuncSetAttribute(gemm4_tc,   cudaFuncAttributeMaxDynamicSharedMemorySize, SM256);

    void *xh,*xl,*xch,*xcl,*ynh,*ynl,*winh,*winl,*wxh,*wxl,*wdth,*wdtl,*wouth,*woutl,*wx2h,*wx2l,*wch,*wcl;
    cudaGetSymbolAddress(&xh,  g_xh);   cudaGetSymbolAddress(&xl,  g_xl);
    cudaGetSymbolAddress(&xch, g_xch);  cudaGetSymbolAddress(&xcl, g_xcl);
    cudaGetSymbolAddress(&ynh, g_ynh);  cudaGetSymbolAddress(&ynl, g_ynl);
    cudaGetSymbolAddress(&winh,g_winh); cudaGetSymbolAddress(&winl,g_winl);
    cudaGetSymbolAddress(&wxh, g_wxh);  cudaGetSymbolAddress(&wxl, g_wxl);
    cudaGetSymbolAddress(&wdth,g_wdth); cudaGetSymbolAddress(&wdtl,g_wdtl);
    cudaGetSymbolAddress(&wouth,g_wouth);cudaGetSymbolAddress(&woutl,g_woutl);
    cudaGetSymbolAddress(&wx2h,g_wx2h); cudaGetSymbolAddress(&wx2l,g_wx2l);
    cudaGetSymbolAddress(&wch, g_wch);  cudaGetSymbolAddress(&wcl, g_wcl);

    static EncFn enc = nullptr;
    if (!enc) enc = get_enc();
    static CUtensorMap m_xh, m_xl, m_xch, m_xcl, m_ynh, m_ynl;
    static CUtensorMap m_winh, m_winl, m_wxh, m_wxl, m_wdth, m_wdtl;
    static CUtensorMap m_wouth, m_woutl, m_wx2h, m_wx2l, m_wch, m_wcl;
    mkmap(enc, &m_xh,   xh,   1024, ROWS, 128);
    mkmap(enc, &m_xl,   xl,   1024, ROWS, 128);
    mkmap(enc, &m_xch,  xch,  2048, ROWS, 128);
    mkmap(enc, &m_xcl,  xcl,  2048, ROWS, 128);
    mkmap(enc, &m_ynh,  ynh,  2048, ROWS, 128);
    mkmap(enc, &m_ynl,  ynl,  2048, ROWS, 128);
    mkmap(enc, &m_winh, winh, 1024, 4096, 256);
    mkmap(enc, &m_winl, winl, 1024, 4096, 256);
    mkmap(enc, &m_wxh,  wxh,  2048, 128,  128);
    mkmap(enc, &m_wxl,  wxl,  2048, 128,  128);
    mkmap(enc, &m_wdth, wdth, 2048, 2048, 128);
    mkmap(enc, &m_wdtl, wdtl, 2048, 2048, 128);
    mkmap(enc, &m_wouth,wouth,2048, 1024, 256);
    mkmap(enc, &m_woutl,woutl,2048, 1024, 256);
    mkmap(enc, &m_wx2h, wx2h, 2048, 2048, 256);
    mkmap(enc, &m_wx2l, wx2l, 2048, 2048, 256);
    mkmap(enc, &m_wch,  wch,  2048, 2048, 256);
    mkmap(enc, &m_wcl,  wcl,  2048, 2048, 256);

    split_x_kernel<<<(ROWS*DMODEL)/256, 256>>>(x);
    wsplit_kernel<<<dim3(4096/32, 1024/32), 256>>>(W_in,  (__nv_bfloat16*)winh, (__nv_bfloat16*)winl, 1024, 4096);
    wsplit_kernel<<<dim3(128/32,  2048/32), 256>>>(W_x,   (__nv_bfloat16*)wxh,  (__nv_bfloat16*)wxl,  2048, 2176);
    wsplit_kernel<<<dim3(2048/32, 2048/32), 256>>>(W_dt,  (__nv_bfloat16*)wdth, (__nv_bfloat16*)wdtl, 2048, 2048);
    wsplit_kernel<<<dim3(1024/32, 2048/32), 256>>>(W_out, (__nv_bfloat16*)wouth,(__nv_bfloat16*)woutl,2048, 1024);
    wsplit_direct<<<(2048*2048)/256, 256>>>(W_x, (__nv_bfloat16*)wx2h, (__nv_bfloat16*)wx2l, 2176, 128, 2048);

    wcombine_tc<<<dim3(8, 16), 512, SM256>>>(m_wdth, m_wdtl, m_wx2h, m_wx2l);
    gemm1_tc<<<dim3(16, 64), 512, SM256>>>(m_xh, m_xl, m_winh, m_winl);
    conv_silu_kernel<<<(ROWS*DINNER)/256, 256>>>(conv_w, conv_b);
    gemm2a_tc<<<dim3(1, 64), 512, SM128>>>(m_xch, m_xcl, m_wxh, m_wxl);
    gemm3_tc<<<dim3(8, 64), 512, SM256>>>(m_xch, m_xcl, m_wch, m_wcl, b_dt);
    scan_phase1<<<BB*NCHUNK*(DINNER/128), 256>>>(A_log);
    scan_combine<<<(BB*DSTATE*DINNER)/256, 256>>>();
    scan_phase3<<<BB*NCHUNK*(DINNER/128), 256>>>(A_log, D_par);
    norm_kernel<<<ROWS, 256>>>(norm_w);
    gemm4_tc<<<dim3(4, 64), 512, SM256>>>(m_ynh, m_ynl, m_wouth, m_woutl, out);
}

// round 14
// speedup vs baseline: 1.0691x; 1.0276x over previous
#include <cuda_runtime.h>
#include <cuda.h>
#include <cuda_bf16.h>
#include <math.h>
#include <stdint.h>
#include <dlfcn.h>

#define BB     2
#define LL     4096
#define DMODEL 1024
#define DSTATE 64
#define DCONV  4
#define DINNER 2048
#define ROWS   (BB*LL)
#define EPSV   1.1920929e-07f
#define CHUNK  128
#define NCHUNK (LL/CHUNK)
#define LOG2E  1.44269504088896340736f

// ---------------- scratch ----------------
__device__ __align__(128) float g_xz [ROWS * (2*DINNER)];
__device__ __align__(128) float g_xc [ROWS * DINNER];
__device__ __align__(128) float g_bc [ROWS * 128];
__device__ __align__(128) float g_dt [ROWS * DINNER];
__device__ __align__(128) float g_y  [ROWS * DINNER];
__device__ __align__(128) float g_E  [BB*NCHUNK*DSTATE*DINNER];
__device__ __align__(128) float g_P  [BB*NCHUNK*DSTATE*DINNER];
__device__ __align__(128) float g_hin[BB*NCHUNK*DSTATE*DINNER];
__device__ __align__(128) __nv_bfloat16 g_xh  [ROWS*DMODEL], g_xl  [ROWS*DMODEL];
__device__ __align__(128) __nv_bfloat16 g_xch [ROWS*DINNER], g_xcl [ROWS*DINNER];
__device__ __align__(128) __nv_bfloat16 g_ynh [ROWS*DINNER], g_ynl [ROWS*DINNER];
__device__ __align__(128) __nv_bfloat16 g_winh [4096*1024], g_winl [4096*1024];
__device__ __align__(128) __nv_bfloat16 g_wxh  [128*2048],  g_wxl  [128*2048];
__device__ __align__(128) __nv_bfloat16 g_wdth [2048*2048], g_wdtl [2048*2048];
__device__ __align__(128) __nv_bfloat16 g_wouth[1024*2048], g_woutl[1024*2048];
__device__ __align__(128) __nv_bfloat16 g_wx2h [2048*2048], g_wx2l [2048*2048];
__device__ __align__(128) __nv_bfloat16 g_wch  [2048*2048], g_wcl  [2048*2048];

// ---------------- device helpers ----------------
__device__ __forceinline__ float ex2f(float x){ float y; asm("ex2.approx.ftz.f32 %0, %1;":"=f"(y):"f"(x)); return y; }
__device__ __forceinline__ float softplus_f(float x){ return x > 20.f ? x : log1pf(expf(x)); }
__device__ __forceinline__ float silu_f(float x){ return x / (1.f + expf(-x)); }
__device__ __forceinline__ uint32_t pack_bf2(float lo, float hi){
    uint32_t r; asm("cvt.rn.bf16x2.f32 %0, %1, %2;":"=r"(r):"f"(hi),"f"(lo)); return r;
}
__device__ __forceinline__ uint32_t smem_u32(const void* p){
    uint32_t a; asm("{ .reg .u64 t; cvta.to.shared.u64 t, %1; cvt.u32.u64 %0, t; }":"=r"(a):"l"(p)); return a;
}
__device__ __forceinline__ void mma_bf16(float (&d)[4], const uint32_t* a, const uint32_t* b){
    asm volatile("mma.sync.aligned.m16n8k16.row.col.f32.bf16.bf16.f32 "
        "{%0,%1,%2,%3}, {%4,%5,%6,%7}, {%8,%9}, {%0,%1,%2,%3};"
        : "+f"(d[0]), "+f"(d[1]), "+f"(d[2]), "+f"(d[3])
        : "r"(a[0]), "r"(a[1]), "r"(a[2]), "r"(a[3]), "r"(b[0]), "r"(b[1]));
}
__device__ __forceinline__ void ldsm4(uint32_t* r, uint32_t addr){
    asm volatile("ldmatrix.sync.aligned.m8n8.x4.shared.b16 {%0,%1,%2,%3}, [%4];"
        : "=r"(r[0]), "=r"(r[1]), "=r"(r[2]), "=r"(r[3]) : "r"(addr));
}
__device__ __forceinline__ void mbar_init(uint32_t a, uint32_t c){
    asm volatile("mbarrier.init.shared.b64 [%0], %1;"::"r"(a),"r"(c):"memory");
}
__device__ __forceinline__ void mbar_wait(uint32_t a, uint32_t par){
    asm volatile("{\n\t.reg .pred P;\n\tW_%=:\n\t"
        "mbarrier.try_wait.parity.acquire.cta.shared::cta.b64 P, [%0], %1, 0x989680;\n\t"
        "@P bra.uni D_%=;\n\tbra.uni W_%=;\n\tD_%=:\n\t}"::"r"(a),"r"(par):"memory");
}
__device__ __forceinline__ void tma2d(uint32_t smem, const CUtensorMap* m, int x, int y, uint32_t mb){
    asm volatile("cp.async.bulk.tensor.2d.shared::cta.global.tile.mbarrier::complete_tx::bytes "
        "[%0], [%1, {%2, %3}], [%4];" :: "r"(smem), "l"(m), "r"(x), "r"(y), "r"(mb) : "memory");
}
__device__ __forceinline__ uint32_t swz128(uint32_t off){ return off ^ ((off >> 3) & 0x70); }

// ---------------- TMA-fed HMMA bf16x3 core: 128 x NT tile, BK=64, 512 thr,
// 2-stage mbarrier pipeline. Stage: Ah@0(16K) Al@16K Bh@32K(NT*128) Bl after.
template<int NT, int NG>   // NG = NT/128
__device__ __forceinline__ void gemm_core_v4(
    const CUtensorMap* tAh, const CUtensorMap* tAl,
    const CUtensorMap* tBh, const CUtensorMap* tBl,
    int rowA, int rowB, int ktot, float (&acc)[4][2*NG][4])
{
    constexpr int STG = 32768 + NT*256;
    extern __shared__ __align__(1024) char smbuf[];
    const uint32_t sm  = (smem_u32(smbuf) + 1023u) & ~1023u;
    const uint32_t mb0 = sm + 2u*STG;
    const int t = threadIdx.x, lane = t & 31, wid = t >> 5;
    const int m0 = (wid & 1)*64, n0 = (wid >> 1)*(16*NG);
    const int lr = lane & 15, lc = lane >> 4;
    const int kch = ktot >> 6;

    if (t == 0){ mbar_init(mb0, 1); mbar_init(mb0 + 8, 1); }
    __syncthreads();

    auto issue = [&](int c, int s){
        if (t == 0){
            const uint32_t mb = mb0 + (uint32_t)s*8u;
            asm volatile("mbarrier.arrive.expect_tx.shared.b64 _, [%0], %1;"
                         :: "r"(mb), "r"((uint32_t)STG) : "memory");
            const uint32_t base = sm + (uint32_t)s*STG;
            const int kx = c*64;
            tma2d(base,                  tAh, kx, rowA, mb);
            tma2d(base + 16384,          tAl, kx, rowA, mb);
            tma2d(base + 32768,          tBh, kx, rowB, mb);
            tma2d(base + 32768 + NT*128, tBl, kx, rowB, mb);
        }
    };
    issue(0, 0);
    issue(1, 1);
    uint32_t ph[2] = {0u, 0u};

    for (int c = 0; c < kch; c++){
        const int s = c & 1;
        mbar_wait(mb0 + (uint32_t)s*8u, ph[s]); ph[s] ^= 1u;
        const uint32_t base = sm + (uint32_t)s*STG;
        #pragma unroll
        for (int ks = 0; ks < 4; ks++){
            const int ch = ks*2 + lc;
            uint32_t bh[NG][4], bl[NG][4];
            #pragma unroll
            for (int g = 0; g < NG; g++){
                uint32_t a = base + 32768 + swz128((uint32_t)((n0 + g*16 + lr)*128 + ch*16));
                ldsm4(bh[g], a);
                ldsm4(bl[g], a + NT*128);
            }
            #pragma unroll
            for (int mt = 0; mt < 4; mt++){
                uint32_t a = base + swz128((uint32_t)((m0 + mt*16 + lr)*128 + ch*16));
                uint32_t ah[4], al[4];
                ldsm4(ah, a);
                ldsm4(al, a + 16384);
                #pragma unroll
                for (int nt = 0; nt < 2*NG; nt++){
                    const int g = nt >> 1, sel = nt & 1;
                    uint32_t bfh[2] = { bh[g][sel], bh[g][sel+2] };
                    uint32_t bfl[2] = { bl[g][sel], bl[g][sel+2] };
                    mma_bf16(acc[mt][nt], ah, bfh);
                    mma_bf16(acc[mt][nt], al, bfh);
                    mma_bf16(acc[mt][nt], ah, bfl);
                }
            }
        }
        __syncthreads();              // all reads of stage s done
        if (c + 2 < kch) issue(c + 2, s);
    }
}

#define EPI3_SETUP(NT, NG) \
    const int lane = threadIdx.x & 31; \
    const int wid  = threadIdx.x >> 5; \
    const int mrow = blockIdx.y * 128 + (wid & 1) * 64 + (lane >> 2); \
    const int ncol = blockIdx.x * NT + (wid >> 1) * (16*NG) + (lane & 3) * 2;

// ---------------- GEMM kernels ----------------
__global__ __launch_bounds__(512, 1) void gemm1_tc(
    const __grid_constant__ CUtensorMap tAh, const __grid_constant__ CUtensorMap tAl,
    const __grid_constant__ CUtensorMap tBh, const __grid_constant__ CUtensorMap tBl){
    float acc[4][4][4] = {};
    gemm_core_v4<256,2>(&tAh,&tAl,&tBh,&tBl, blockIdx.y*128, blockIdx.x*256, DMODEL, acc);
    EPI3_SETUP(256, 2);
    #pragma unroll
    for (int mt = 0; mt < 4; mt++)
        #pragma unroll
        for (int nt = 0; nt < 4; nt++){
            int r = mrow + mt*16, cc = ncol + nt*8;
            *(float2*)&g_xz[(size_t)r*(2*DINNER) + cc]     = make_float2(acc[mt][nt][0], acc[mt][nt][1]);
            *(float2*)&g_xz[(size_t)(r+8)*(2*DINNER) + cc] = make_float2(acc[mt][nt][2], acc[mt][nt][3]);
        }
}
__global__ __launch_bounds__(512, 1) void gemm2a_tc(
    const __grid_constant__ CUtensorMap tAh, const __grid_constant__ CUtensorMap tAl,
    const __grid_constant__ CUtensorMap tBh, const __grid_constant__ CUtensorMap tBl){
    float acc[4][2][4] = {};
    gemm_core_v4<128,1>(&tAh,&tAl,&tBh,&tBl, blockIdx.y*128, 0, DINNER, acc);
    EPI3_SETUP(128, 1);
    #pragma unroll
    for (int mt = 0; mt < 4; mt++)
        #pragma unroll
        for (int nt = 0; nt < 2; nt++){
            int r = mrow + mt*16, cc = ncol + nt*8;
            *(float2*)&g_bc[(size_t)r*128 + cc]     = make_float2(acc[mt][nt][0], acc[mt][nt][1]);
            *(float2*)&g_bc[(size_t)(r+8)*128 + cc] = make_float2(acc[mt][nt][2], acc[mt][nt][3]);
        }
}
__global__ __launch_bounds__(512, 1) void wcombine_tc(
    const __grid_constant__ CUtensorMap tAh, const __grid_constant__ CUtensorMap tAl,
    const __grid_constant__ CUtensorMap tBh, const __grid_constant__ CUtensorMap tBl){
    float acc[4][4][4] = {};
    gemm_core_v4<256,2>(&tAh,&tAl,&tBh,&tBl, blockIdx.y*128, blockIdx.x*256, 2048, acc);
    EPI3_SETUP(256, 2);
    #pragma unroll
    for (int mt = 0; mt < 4; mt++)
        #pragma unroll
        for (int nt = 0; nt < 4; nt++){
            int r = mrow + mt*16, cc = ncol + nt*8;
            #pragma unroll
            for (int hrow = 0; hrow < 2; hrow++){
                float v0 = acc[mt][nt][2*hrow], v1 = acc[mt][nt][2*hrow+1];
                uint32_t hp = pack_bf2(v0, v1);
                uint32_t lp = pack_bf2(v0 - __uint_as_float(hp << 16),
                                       v1 - __uint_as_float(hp & 0xFFFF0000u));
                size_t o = (size_t)(r + 8*hrow)*2048 + cc;
                *(uint32_t*)&g_wch[o] = hp;
                *(uint32_t*)&g_wcl[o] = lp;
            }
        }
}
__global__ __launch_bounds__(512, 1) void gemm3_tc(
    const __grid_constant__ CUtensorMap tAh, const __grid_constant__ CUtensorMap tAl,
    const __grid_constant__ CUtensorMap tBh, const __grid_constant__ CUtensorMap tBl,
    const float* __restrict__ b_dt){
    float acc[4][4][4] = {};
    gemm_core_v4<256,2>(&tAh,&tAl,&tBh,&tBl, blockIdx.y*128, blockIdx.x*256, DINNER, acc);
    EPI3_SETUP(256, 2);
    #pragma unroll
    for (int mt = 0; mt < 4; mt++)
        #pragma unroll
        for (int nt = 0; nt < 4; nt++){
            int r = mrow + mt*16, cc = ncol + nt*8;
            float b0 = b_dt[cc], b1 = b_dt[cc+1];
            g_dt[(size_t)r*DINNER + cc]       = softplus_f(acc[mt][nt][0] + b0);
            g_dt[(size_t)r*DINNER + cc + 1]   = softplus_f(acc[mt][nt][1] + b1);
            g_dt[(size_t)(r+8)*DINNER + cc]   = softplus_f(acc[mt][nt][2] + b0);
            g_dt[(size_t)(r+8)*DINNER + cc+1] = softplus_f(acc[mt][nt][3] + b1);
        }
}
__global__ __launch_bounds__(512, 1) void gemm4_tc(
    const __grid_constant__ CUtensorMap tAh, const __grid_constant__ CUtensorMap tAl,
    const __grid_constant__ CUtensorMap tBh, const __grid_constant__ CUtensorMap tBl,
    float* __restrict__ out){
    float acc[4][4][4] = {};
    gemm_core_v4<256,2>(&tAh,&tAl,&tBh,&tBl, blockIdx.y*128, blockIdx.x*256, DINNER, acc);
    EPI3_SETUP(256, 2);
    #pragma unroll
    for (int mt = 0; mt < 4; mt++)
        #pragma unroll
        for (int nt = 0; nt < 4; nt++){
            int r = mrow + mt*16, cc = ncol + nt*8;
            *(float2*)&out[(size_t)r*DMODEL + cc]     = make_float2(acc[mt][nt][0], acc[mt][nt][1]);
            *(float2*)&out[(size_t)(r+8)*DMODEL + cc] = make_float2(acc[mt][nt][2], acc[mt][nt][3]);
        }
}

// ---------------- prep ----------------
__global__ __launch_bounds__(256) void split_x_kernel(const float* __restrict__ x){
    int idx = blockIdx.x*256 + threadIdx.x;
    float v = x[idx];
    __nv_bfloat16 h = __float2bfloat16(v);
    g_xh[idx] = h;
    g_xl[idx] = __float2bfloat16(v - __bfloat162float(h));
}
__global__ __launch_bounds__(256) void wsplit_kernel(const float* __restrict__ W,
                                                     __nv_bfloat16* __restrict__ oh,
                                                     __nv_bfloat16* __restrict__ ol,
                                                     int K, int N){
    __shared__ float tl[32][33];
    const int n0 = blockIdx.x*32, k0 = blockIdx.y*32;
    const int tx = threadIdx.x & 31, ty = threadIdx.x >> 5;
    #pragma unroll
    for (int i = 0; i < 4; i++)
        tl[ty + i*8][tx] = W[(size_t)(k0 + ty + i*8)*N + n0 + tx];
    __syncthreads();
    #pragma unroll
    for (int i = 0; i < 4; i++){
        int nl = ty + i*8;
        float v = tl[tx][nl];
        __nv_bfloat16 h = __float2bfloat16(v);
        size_t o = (size_t)(n0 + nl)*K + k0 + tx;
        oh[o] = h;
        ol[o] = __float2bfloat16(v - __bfloat162float(h));
    }
}
__global__ __launch_bounds__(256) void wsplit_direct(const float* __restrict__ W,
                                                     __nv_bfloat16* __restrict__ oh,
                                                     __nv_bfloat16* __restrict__ ol,
                                                     int ldw, int coloff, int JCOLS){
    int idx = blockIdx.x*256 + threadIdx.x;
    int k = idx / JCOLS, j = idx - k*JCOLS;
    float v = W[(size_t)k*ldw + coloff + j];
    __nv_bfloat16 h = __float2bfloat16(v);
    oh[idx] = h;
    ol[idx] = __float2bfloat16(v - __bfloat162float(h));
}

// ---------------- conv + SiLU ----------------
__global__ __launch_bounds__(256) void conv_silu_kernel(const float* __restrict__ cw,
                                                        const float* __restrict__ cb){
    int idx = blockIdx.x*256 + threadIdx.x;
    int d   = idx & (DINNER - 1);
    int row = idx >> 11;
    int t   = row & (LL - 1);
    float acc = cb[d];
    #pragma unroll
    for (int k = 0; k < DCONV; k++){
        int tt = t - (DCONV - 1) + k;
        if (tt >= 0)
            acc = fmaf(g_xz[(size_t)(row - (DCONV - 1) + k)*(2*DINNER) + d], cw[d*DCONV + k], acc);
    }
    float v = silu_f(acc);
    g_xc[idx] = v;
    __nv_bfloat16 h = __float2bfloat16(v);
    g_xch[idx] = h;
    g_xcl[idx] = __float2bfloat16(v - __bfloat162float(h));
}

// ---------------- scan ----------------
__global__ __launch_bounds__(256) void scan_phase1(const float* __restrict__ A_log){
    const int blk = blockIdx.x;
    const int dgrp = blk & 15, chunk = (blk >> 4) & (NCHUNK-1), b = blk >> 9;
    const int tid = threadIdx.x, dloc = tid >> 1, half = tid & 1;
    const int d = dgrp*128 + dloc, s0 = half*32;
    const float u = -expf(A_log[d*DSTATE]) * LOG2E;
    float a2[32], h[32], p[32];
    bool fast = true;
    #pragma unroll
    for (int i = 0; i < 32; i++){
        a2[i] = -expf(A_log[d*DSTATE + s0 + i]) * LOG2E;
        float ex = u * (float)(s0 + i + 1);
        fast = fast && (fabsf(a2[i] - ex) <= 1e-6f*fabsf(ex) + 1e-30f);
        h[i] = 0.f; p[i] = 1.f;
    }
    __shared__ float sBC[2][128];
    const int rowbase = b*LL + chunk*CHUNK;
    for (int t = 0; t < CHUNK; t++){
        const int row = rowbase + t;
        if (tid < 128) sBC[t & 1][tid] = g_bc[(size_t)row*128 + tid];
        __syncthreads();
        const float dtv = g_dt[(size_t)row*DINNER + d];
        const float uv  = dtv * g_xc[(size_t)row*DINNER + d];
        const float* Bv = &sBC[t & 1][s0];
        if (fast){
            float q = ex2f(dtv * u);
            float q2=q*q, q4=q2*q2, q8=q4*q4, q16=q8*q8;
            float dA0;
            if (s0 == 0) dA0 = q;
            else { float q32=q16*q16; dA0 = q32*q; }
            float dA1 = dA0*q16;
            #pragma unroll
            for (int i = 0; i < 16; i++){
                p[i]    *= dA0; h[i]    = fmaf(dA0, h[i],    uv * Bv[i]);
                p[i+16] *= dA1; h[i+16] = fmaf(dA1, h[i+16], uv * Bv[i+16]);
                dA0 *= q; dA1 *= q;
            }
        } else {
            #pragma unroll
            for (int i = 0; i < 32; i++){
                float dA = ex2f(dtv * a2[i]);
                p[i] *= dA;
                h[i] = fmaf(dA, h[i], uv * Bv[i]);
            }
        }
    }
    const int base = ((b*NCHUNK + chunk)*DSTATE + s0)*DINNER + d;
    #pragma unroll
    for (int i = 0; i < 32; i++){ g_E[base + i*DINNER] = h[i]; g_P[base + i*DINNER] = p[i]; }
}
__global__ __launch_bounds__(256) void scan_combine(){
    const int idx = blockIdx.x*256 + threadIdx.x;
    const int d = idx & (DINNER-1), bs = idx >> 11, b = bs >> 6, s = bs & 63;
    float h = 0.f;
    for (int j = 0; j < NCHUNK; j++){
        const int o = ((b*NCHUNK + j)*DSTATE + s)*DINNER + d;
        g_hin[o] = h;
        h = fmaf(g_P[o], h, g_E[o]);
    }
}
__global__ __launch_bounds__(256) void scan_phase3(const float* __restrict__ A_log,
                                                   const float* __restrict__ D_param){
    const int blk = blockIdx.x;
    const int dgrp = blk & 15, chunk = (blk >> 4) & (NCHUNK-1), b = blk >> 9;
    const int tid = threadIdx.x, dloc = tid >> 1, half = tid & 1;
    const int d = dgrp*128 + dloc, s0 = half*32;
    const float u = -expf(A_log[d*DSTATE]) * LOG2E;
    float a2[32], h[32];
    bool fast = true;
    const int hbase = ((b*NCHUNK + chunk)*DSTATE + s0)*DINNER + d;
    #pragma unroll
    for (int i = 0; i < 32; i++){
        a2[i] = -expf(A_log[d*DSTATE + s0 + i]) * LOG2E;
        float ex = u * (float)(s0 + i + 1);
        fast = fast && (fabsf(a2[i] - ex) <= 1e-6f*fabsf(ex) + 1e-30f);
        h[i]  = g_hin[hbase + i*DINNER];
    }
    const float Dv = D_param[d];
    __shared__ float sBC[2][128];
    const int rowbase = b*LL + chunk*CHUNK;
    for (int t = 0; t < CHUNK; t++){
        const int row = rowbase + t;
        if (tid < 128) sBC[t & 1][tid] = g_bc[(size_t)row*128 + tid];
        __syncthreads();
        const float dtv = g_dt[(size_t)row*DINNER + d];
        const float xcv = g_xc[(size_t)row*DINNER + d];
        const float uv  = dtv * xcv;
        const float* Bv = &sBC[t & 1][s0];
        const float* Cv = &sBC[t & 1][64 + s0];
        float yacc = 0.f;
        if (fast){
            float q = ex2f(dtv * u);
            float q2=q*q, q4=q2*q2, q8=q4*q4, q16=q8*q8;
            float dA0;
            if (s0 == 0) dA0 = q;
            else { float q32=q16*q16; dA0 = q32*q; }
            float dA1 = dA0*q16;
            #pragma unroll
            for (int i = 0; i < 16; i++){
                h[i]    = fmaf(dA0, h[i],    uv * Bv[i]);
                yacc    = fmaf(h[i],    Cv[i],    yacc);
                h[i+16] = fmaf(dA1, h[i+16], uv * Bv[i+16]);
                yacc    = fmaf(h[i+16], Cv[i+16], yacc);
                dA0 *= q; dA1 *= q;
            }
        } else {
            #pragma unroll
            for (int i = 0; i < 32; i++){
                float dA = ex2f(dtv * a2[i]);
                h[i] = fmaf(dA, h[i], uv * Bv[i]);
                yacc = fmaf(h[i], Cv[i], yacc);
            }
        }
        yacc += __shfl_xor_sync(0xffffffffu, yacc, 1);
        if (half == 0){
            const size_t o = (size_t)row*DINNER + d;
            g_y[o] = yacc + Dv * xcv;
        }
    }
}

// ---------------- RMSNorm + silu(z) gate -> split bf16 ----------------
__global__ __launch_bounds__(256) void norm_kernel(const float* __restrict__ norm_w){
    const int row = blockIdx.x, tid = threadIdx.x;
    const size_t base = (size_t)row*DINNER;
    float ss = 0.f;
    for (int i = tid; i < DINNER; i += 256){
        float v = g_y[base + i];
        ss = fmaf(v, v, ss);
    }
    #pragma unroll
    for (int o = 16; o; o >>= 1) ss += __shfl_xor_sync(0xffffffffu, ss, o);
    __shared__ float red[8];
    __shared__ float s_inv;
    if ((tid & 31) == 0) red[tid >> 5] = ss;
    __syncthreads();
    if (tid == 0){
        float t = 0.f;
        #pragma unroll
        for (int i = 0; i < 8; i++) t += red[i];
        s_inv = rsqrtf(t/(float)DINNER + EPSV);
    }
    __syncthreads();
    const float inv = s_inv;
    for (int i = tid; i < DINNER; i += 256){
        float v  = g_y[base + i]*inv*norm_w[i];
        float zv = g_xz[(size_t)row*(2*DINNER) + DINNER + i];
        float yv = v*silu_f(zv);
        __nv_bfloat16 h = __float2bfloat16(yv);
        g_ynh[base + i] = h;
        g_ynl[base + i] = __float2bfloat16(yv - __bfloat162float(h));
    }
}

// ---------------- host-side tensormap builder (dlopen, no -lcuda) ----------
typedef CUresult (*EncFn)(CUtensorMap*, CUtensorMapDataType, cuuint32_t, void*,
    const cuuint64_t*, const cuuint64_t*, const cuuint32_t*, const cuuint32_t*,
    CUtensorMapInterleave, CUtensorMapSwizzle, CUtensorMapL2promotion, CUtensorMapFloatOOBfill);

static EncFn get_enc(){
    void* h = dlopen("libcuda.so.1", RTLD_LAZY | RTLD_GLOBAL);
    if (!h) h = dlopen("libcuda.so", RTLD_LAZY | RTLD_GLOBAL);
    if (!h) return nullptr;
    return (EncFn)dlsym(h, "cuTensorMapEncodeTiled");
}
static void mkmap(EncFn f, CUtensorMap* m, void* p, uint64_t K, uint64_t R, uint32_t boxR){
    if (!f || !p) return;   // degrade to wrong-answer, never segfault the harness
    cuuint64_t gd[2] = {K, R};
    cuuint64_t gs[1] = {K*2};
    cuuint32_t bd[2] = {64, boxR};
    cuuint32_t es[2] = {1, 1};
    f(m, CU_TENSOR_MAP_DATA_TYPE_BFLOAT16, 2, p, gd, gs, bd, es,
      CU_TENSOR_MAP_INTERLEAVE_NONE, CU_TENSOR_MAP_SWIZZLE_128B,
      CU_TENSOR_MAP_L2_PROMOTION_L2_128B, CU_TENSOR_MAP_FLOAT_OOB_FILL_NONE);
}

// ---------------- launch ----------------
extern "C" void kernel_launch(void* const* d_in, const int* in_sizes, int n_in,
                              void* d_out, int out_size){
    const float* x      = (const float*)d_in[0];
    const float* W_in   = (const float*)d_in[1];
    const float* conv_w = (const float*)d_in[2];
    const float* conv_b = (const float*)d_in[3];
    const float* W_x    = (const float*)d_in[4];
    const float* W_dt   = (const float*)d_in[5];
    const float* b_dt   = (const float*)d_in[6];
    const float* A_log  = (const float*)d_in[7];
    const float* D_par  = (const float*)d_in[8];
    const float* W_out  = (const float*)d_in[9];
    const float* norm_w = (const float*)d_in[10];
    float* out = (float*)d_out;

    const int STG256 = 32768 + 256*256;            // 98304
    const int STG128 = 32768 + 128*256;            // 65536
    const int SM256  = 2*STG256 + 1024 + 64;       // 197,696
    const int SM128  = 2*STG128 + 1024 + 64;       // 132,160
    cudaFuncSetAttribute(gemm1_tc,   cudaFuncAttributeMaxDynamicSharedMemorySize, SM256);
    cudaFuncSetAttribute(gemm2a_tc,  cudaFuncAttributeMaxDynamicSharedMemorySize, SM128);
    cudaFuncSetAttribute(wcombine_tc,cudaFuncAttributeMaxDynamicSharedMemorySize, SM256);
    cudaFuncSetAttribute(gemm3_tc,   cudaFuncAttributeMaxDynamicSharedMemorySize, SM256);
    cudaFuncSetAttribute(gemm4_tc,   cudaFuncAttributeMaxDynamicSharedMemorySize, SM256);

    void *xh,*xl,*xch,*xcl,*ynh,*ynl,*winh,*winl,*wxh,*wxl,*wdth,*wdtl,*wouth,*woutl,*wx2h,*wx2l,*wch,*wcl;
    cudaGetSymbolAddress(&xh,  g_xh);   cudaGetSymbolAddress(&xl,  g_xl);
    cudaGetSymbolAddress(&xch, g_xch);  cudaGetSymbolAddress(&xcl, g_xcl);
    cudaGetSymbolAddress(&ynh, g_ynh);  cudaGetSymbolAddress(&ynl, g_ynl);
    cudaGetSymbolAddress(&winh,g_winh); cudaGetSymbolAddress(&winl,g_winl);
    cudaGetSymbolAddress(&wxh, g_wxh);  cudaGetSymbolAddress(&wxl, g_wxl);
    cudaGetSymbolAddress(&wdth,g_wdth); cudaGetSymbolAddress(&wdtl,g_wdtl);
    cudaGetSymbolAddress(&wouth,g_wouth);cudaGetSymbolAddress(&woutl,g_woutl);
    cudaGetSymbolAddress(&wx2h,g_wx2h); cudaGetSymbolAddress(&wx2l,g_wx2l);
    cudaGetSymbolAddress(&wch, g_wch);  cudaGetSymbolAddress(&wcl, g_wcl);

    static EncFn enc = nullptr;
    if (!enc) enc = get_enc();
    static CUtensorMap m_xh, m_xl, m_xch, m_xcl, m_ynh, m_ynl;
    static CUtensorMap m_winh, m_winl, m_wxh, m_wxl, m_wdth, m_wdtl;
    static CUtensorMap m_wouth, m_woutl, m_wx2h, m_wx2l, m_wch, m_wcl;
    mkmap(enc, &m_xh,   xh,   1024, ROWS, 128);
    mkmap(enc, &m_xl,   xl,   1024, ROWS, 128);
    mkmap(enc, &m_xch,  xch,  2048, ROWS, 128);
    mkmap(enc, &m_xcl,  xcl,  2048, ROWS, 128);
    mkmap(enc, &m_ynh,  ynh,  2048, ROWS, 128);
    mkmap(enc, &m_ynl,  ynl,  2048, ROWS, 128);
    mkmap(enc, &m_winh, winh, 1024, 4096, 256);
    mkmap(enc, &m_winl, winl, 1024, 4096, 256);
    mkmap(enc, &m_wxh,  wxh,  2048, 128,  128);
    mkmap(enc, &m_wxl,  wxl,  2048, 128,  128);
    mkmap(enc, &m_wdth, wdth, 2048, 2048, 128);
    mkmap(enc, &m_wdtl, wdtl, 2048, 2048, 128);
    mkmap(enc, &m_wouth,wouth,2048, 1024, 256);
    mkmap(enc, &m_woutl,woutl,2048, 1024, 256);
    mkmap(enc, &m_wx2h, wx2h, 2048, 2048, 256);
    mkmap(enc, &m_wx2l, wx2l, 2048, 2048, 256);
    mkmap(enc, &m_wch,  wch,  2048, 2048, 256);
    mkmap(enc, &m_wcl,  wcl,  2048, 2048, 256);

    // side stream + events for capture-safe fork/join
    static cudaStream_t sB = nullptr;
    static cudaEvent_t evF1 = nullptr, evJ1 = nullptr, evF2 = nullptr, evJ2 = nullptr;
    if (!sB){
        cudaStreamCreateWithFlags(&sB, cudaStreamNonBlocking);
        cudaEventCreateWithFlags(&evF1, cudaEventDisableTiming);
        cudaEventCreateWithFlags(&evJ1, cudaEventDisableTiming);
        cudaEventCreateWithFlags(&evF2, cudaEventDisableTiming);
        cudaEventCreateWithFlags(&evJ2, cudaEventDisableTiming);
    }

    // default stream: x split + W_in split (gemm1 deps)
    split_x_kernel<<<(ROWS*DMODEL)/256, 256>>>(x);
    wsplit_kernel<<<dim3(4096/32, 1024/32), 256>>>(W_in,  (__nv_bfloat16*)winh, (__nv_bfloat16*)winl, 1024, 4096);

    // fork: remaining weight prep + wcombine on side stream, overlapping gemm1
    cudaEventRecord(evF1, 0);
    cudaStreamWaitEvent(sB, evF1, 0);
    wsplit_kernel<<<dim3(128/32,  2048/32), 256, 0, sB>>>(W_x,   (__nv_bfloat16*)wxh,  (__nv_bfloat16*)wxl,  2048, 2176);
    wsplit_kernel<<<dim3(2048/32, 2048/32), 256, 0, sB>>>(W_dt,  (__nv_bfloat16*)wdth, (__nv_bfloat16*)wdtl, 2048, 2048);
    wsplit_kernel<<<dim3(1024/32, 2048/32), 256, 0, sB>>>(W_out, (__nv_bfloat16*)wouth,(__nv_bfloat16*)woutl,2048, 1024);
    wsplit_direct<<<(2048*2048)/256, 256, 0, sB>>>(W_x, (__nv_bfloat16*)wx2h, (__nv_bfloat16*)wx2l, 2176, 128, 2048);
    wcombine_tc<<<dim3(8, 16), 512, SM256, sB>>>(m_wdth, m_wdtl, m_wx2h, m_wx2l);
    cudaEventRecord(evJ1, sB);

    gemm1_tc<<<dim3(16, 64), 512, SM256>>>(m_xh, m_xl, m_winh, m_winl);
    conv_silu_kernel<<<(ROWS*DINNER)/256, 256>>>(conv_w, conv_b);
    cudaStreamWaitEvent(0, evJ1, 0);      // join: wch/wxh ready

    // fork: gemm2a concurrent with gemm3
    cudaEventRecord(evF2, 0);
    cudaStreamWaitEvent(sB, evF2, 0);
    gemm2a_tc<<<dim3(1, 64), 512, SM128, sB>>>(m_xch, m_xcl, m_wxh, m_wxl);
    cudaEventRecord(evJ2, sB);

    gemm3_tc<<<dim3(8, 64), 512, SM256>>>(m_xch, m_xcl, m_wch, m_wcl, b_dt);
    cudaStreamWaitEvent(0, evJ2, 0);      // join: bc ready

    scan_phase1<<<BB*NCHUNK*(DINNER/128), 256>>>(A_log);
    scan_combine<<<(BB*DSTATE*DINNER)/256, 256>>>();
    scan_phase3<<<BB*NCHUNK*(DINNER/128), 256>>>(A_log, D_par);
    norm_kernel<<<ROWS, 256>>>(norm_w);
    gemm4_tc<<<dim3(4, 64), 512, SM256>>>(m_ynh, m_ynl, m_wouth, m_woutl, out);
}

// round 15
// speedup vs baseline: 1.2368x; 1.1569x over previous
#include <cuda_runtime.h>
#include <cuda.h>
#include <cuda_bf16.h>
#include <math.h>
#include <stdint.h>
#include <dlfcn.h>

#define BB     2
#define LL     4096
#define DMODEL 1024
#define DSTATE 64
#define DCONV  4
#define DINNER 2048
#define ROWS   (BB*LL)
#define EPSV   1.1920929e-07f
#define CHUNK  128
#define NCHUNK (LL/CHUNK)
#define LOG2E  1.44269504088896340736f

// ---------------- scratch ----------------
__device__ __align__(128) float g_xz [ROWS * (2*DINNER)];
__device__ __align__(128) float g_xc [ROWS * DINNER];
__device__ __align__(128) float g_bc [ROWS * 128];
__device__ __align__(128) float g_dt [ROWS * DINNER];
__device__ __align__(128) float g_y  [ROWS * DINNER];
__device__ __align__(128) float g_E  [BB*NCHUNK*DSTATE*DINNER];
__device__ __align__(128) float g_P  [BB*NCHUNK*DSTATE*DINNER];
__device__ __align__(128) float g_hin[BB*NCHUNK*DSTATE*DINNER];
__device__ __align__(128) __nv_bfloat16 g_xh  [ROWS*DMODEL], g_xl  [ROWS*DMODEL];
__device__ __align__(128) __nv_bfloat16 g_xch [ROWS*DINNER], g_xcl [ROWS*DINNER];
__device__ __align__(128) __nv_bfloat16 g_ynh [ROWS*DINNER], g_ynl [ROWS*DINNER];
__device__ __align__(128) __nv_bfloat16 g_winh [4096*1024], g_winl [4096*1024];
__device__ __align__(128) __nv_bfloat16 g_wxh  [128*2048],  g_wxl  [128*2048];
__device__ __align__(128) __nv_bfloat16 g_wdth [2048*2048], g_wdtl [2048*2048];
__device__ __align__(128) __nv_bfloat16 g_wouth[1024*2048], g_woutl[1024*2048];
__device__ __align__(128) __nv_bfloat16 g_wx2h [2048*2048], g_wx2l [2048*2048];
__device__ __align__(128) __nv_bfloat16 g_wch  [2048*2048], g_wcl  [2048*2048];

// ---------------- device helpers ----------------
__device__ __forceinline__ float ex2f(float x){ float y; asm("ex2.approx.ftz.f32 %0, %1;":"=f"(y):"f"(x)); return y; }
__device__ __forceinline__ float softplus_f(float x){ return x > 20.f ? x : log1pf(expf(x)); }
__device__ __forceinline__ float silu_f(float x){ return x / (1.f + expf(-x)); }
__device__ __forceinline__ uint32_t pack_bf2(float lo, float hi){
    uint32_t r; asm("cvt.rn.bf16x2.f32 %0, %1, %2;":"=r"(r):"f"(hi),"f"(lo)); return r;
}
__device__ __forceinline__ uint32_t smem_u32(const void* p){
    uint32_t a; asm("{ .reg .u64 t; cvta.to.shared.u64 t, %1; cvt.u32.u64 %0, t; }":"=r"(a):"l"(p)); return a;
}
__device__ __forceinline__ void mma_bf16(float (&d)[4], const uint32_t* a, const uint32_t* b){
    asm volatile("mma.sync.aligned.m16n8k16.row.col.f32.bf16.bf16.f32 "
        "{%0,%1,%2,%3}, {%4,%5,%6,%7}, {%8,%9}, {%0,%1,%2,%3};"
        : "+f"(d[0]), "+f"(d[1]), "+f"(d[2]), "+f"(d[3])
        : "r"(a[0]), "r"(a[1]), "r"(a[2]), "r"(a[3]), "r"(b[0]), "r"(b[1]));
}
__device__ __forceinline__ void ldsm4(uint32_t* r, uint32_t addr){
    asm volatile("ldmatrix.sync.aligned.m8n8.x4.shared.b16 {%0,%1,%2,%3}, [%4];"
        : "=r"(r[0]), "=r"(r[1]), "=r"(r[2]), "=r"(r[3]) : "r"(addr));
}
__device__ __forceinline__ void mbar_init(uint32_t a, uint32_t c){
    asm volatile("mbarrier.init.shared.b64 [%0], %1;"::"r"(a),"r"(c):"memory");
}
__device__ __forceinline__ void mbar_wait(uint32_t a, uint32_t par){
    asm volatile("{\n\t.reg .pred P;\n\tW_%=:\n\t"
        "mbarrier.try_wait.parity.acquire.cta.shared::cta.b64 P, [%0], %1, 0x989680;\n\t"
        "@P bra.uni D_%=;\n\tbra.uni W_%=;\n\tD_%=:\n\t}"::"r"(a),"r"(par):"memory");
}
__device__ __forceinline__ void tma2d(uint32_t smem, const CUtensorMap* m, int x, int y, uint32_t mb){
    asm volatile("cp.async.bulk.tensor.2d.shared::cta.global.tile.mbarrier::complete_tx::bytes "
        "[%0], [%1, {%2, %3}], [%4];" :: "r"(smem), "l"(m), "r"(x), "r"(y), "r"(mb) : "memory");
}
__device__ __forceinline__ uint32_t swz128(uint32_t off){ return off ^ ((off >> 3) & 0x70); }

// ---------------- TMA-fed HMMA bf16x3 core: 128 x NT tile, BK=64, 512 thr ----
template<int NT, int NG>   // NG = NT/128
__device__ __forceinline__ void gemm_core_v4(
    const CUtensorMap* tAh, const CUtensorMap* tAl,
    const CUtensorMap* tBh, const CUtensorMap* tBl,
    int rowA, int rowB, int ktot, float (&acc)[4][2*NG][4])
{
    constexpr int STG = 32768 + NT*256;
    extern __shared__ __align__(1024) char smbuf[];
    const uint32_t sm  = (smem_u32(smbuf) + 1023u) & ~1023u;
    const uint32_t mb0 = sm + 2u*STG;
    const int t = threadIdx.x, lane = t & 31, wid = t >> 5;
    const int m0 = (wid & 1)*64, n0 = (wid >> 1)*(16*NG);
    const int lr = lane & 15, lc = lane >> 4;
    const int kch = ktot >> 6;

    if (t == 0){ mbar_init(mb0, 1); mbar_init(mb0 + 8, 1); }
    __syncthreads();

    auto issue = [&](int c, int s){
        if (t == 0){
            const uint32_t mb = mb0 + (uint32_t)s*8u;
            asm volatile("mbarrier.arrive.expect_tx.shared.b64 _, [%0], %1;"
                         :: "r"(mb), "r"((uint32_t)STG) : "memory");
            const uint32_t base = sm + (uint32_t)s*STG;
            const int kx = c*64;
            tma2d(base,                  tAh, kx, rowA, mb);
            tma2d(base + 16384,          tAl, kx, rowA, mb);
            tma2d(base + 32768,          tBh, kx, rowB, mb);
            tma2d(base + 32768 + NT*128, tBl, kx, rowB, mb);
        }
    };
    issue(0, 0);
    issue(1, 1);
    uint32_t ph[2] = {0u, 0u};

    for (int c = 0; c < kch; c++){
        const int s = c & 1;
        mbar_wait(mb0 + (uint32_t)s*8u, ph[s]); ph[s] ^= 1u;
        const uint32_t base = sm + (uint32_t)s*STG;
        #pragma unroll
        for (int ks = 0; ks < 4; ks++){
            const int ch = ks*2 + lc;
            uint32_t bh[NG][4], bl[NG][4];
            #pragma unroll
            for (int g = 0; g < NG; g++){
                uint32_t a = base + 32768 + swz128((uint32_t)((n0 + g*16 + lr)*128 + ch*16));
                ldsm4(bh[g], a);
                ldsm4(bl[g], a + NT*128);
            }
            #pragma unroll
            for (int mt = 0; mt < 4; mt++){
                uint32_t a = base + swz128((uint32_t)((m0 + mt*16 + lr)*128 + ch*16));
                uint32_t ah[4], al[4];
                ldsm4(ah, a);
                ldsm4(al, a + 16384);
                #pragma unroll
                for (int nt = 0; nt < 2*NG; nt++){
                    const int g = nt >> 1, sel = nt & 1;
                    uint32_t bfh[2] = { bh[g][sel], bh[g][sel+2] };
                    uint32_t bfl[2] = { bl[g][sel], bl[g][sel+2] };
                    mma_bf16(acc[mt][nt], ah, bfh);
                    mma_bf16(acc[mt][nt], al, bfh);
                    mma_bf16(acc[mt][nt], ah, bfl);
                }
            }
        }
        __syncthreads();
        if (c + 2 < kch) issue(c + 2, s);
    }
}

#define EPI3_SETUP(NT, NG, RO) \
    const int lane = threadIdx.x & 31; \
    const int wid  = threadIdx.x >> 5; \
    const int mrow = (RO) + blockIdx.y * 128 + (wid & 1) * 64 + (lane >> 2); \
    const int ncol = blockIdx.x * NT + (wid >> 1) * (16*NG) + (lane & 3) * 2;

// ---------------- GEMM kernels ----------------
__global__ __launch_bounds__(512, 1) void gemm1_tc(
    const __grid_constant__ CUtensorMap tAh, const __grid_constant__ CUtensorMap tAl,
    const __grid_constant__ CUtensorMap tBh, const __grid_constant__ CUtensorMap tBl){
    float acc[4][4][4] = {};
    gemm_core_v4<256,2>(&tAh,&tAl,&tBh,&tBl, blockIdx.y*128, blockIdx.x*256, DMODEL, acc);
    EPI3_SETUP(256, 2, 0);
    #pragma unroll
    for (int mt = 0; mt < 4; mt++)
        #pragma unroll
        for (int nt = 0; nt < 4; nt++){
            int r = mrow + mt*16, cc = ncol + nt*8;
            *(float2*)&g_xz[(size_t)r*(2*DINNER) + cc]     = make_float2(acc[mt][nt][0], acc[mt][nt][1]);
            *(float2*)&g_xz[(size_t)(r+8)*(2*DINNER) + cc] = make_float2(acc[mt][nt][2], acc[mt][nt][3]);
        }
}
__global__ __launch_bounds__(512, 1) void gemm2a_tc(
    const __grid_constant__ CUtensorMap tAh, const __grid_constant__ CUtensorMap tAl,
    const __grid_constant__ CUtensorMap tBh, const __grid_constant__ CUtensorMap tBl,
    int row0){
    float acc[4][2][4] = {};
    gemm_core_v4<128,1>(&tAh,&tAl,&tBh,&tBl, row0 + blockIdx.y*128, 0, DINNER, acc);
    EPI3_SETUP(128, 1, row0);
    #pragma unroll
    for (int mt = 0; mt < 4; mt++)
        #pragma unroll
        for (int nt = 0; nt < 2; nt++){
            int r = mrow + mt*16, cc = ncol + nt*8;
            *(float2*)&g_bc[(size_t)r*128 + cc]     = make_float2(acc[mt][nt][0], acc[mt][nt][1]);
            *(float2*)&g_bc[(size_t)(r+8)*128 + cc] = make_float2(acc[mt][nt][2], acc[mt][nt][3]);
        }
}
__global__ __launch_bounds__(512, 1) void wcombine_tc(
    const __grid_constant__ CUtensorMap tAh, const __grid_constant__ CUtensorMap tAl,
    const __grid_constant__ CUtensorMap tBh, const __grid_constant__ CUtensorMap tBl){
    float acc[4][4][4] = {};
    gemm_core_v4<256,2>(&tAh,&tAl,&tBh,&tBl, blockIdx.y*128, blockIdx.x*256, 2048, acc);
    EPI3_SETUP(256, 2, 0);
    #pragma unroll
    for (int mt = 0; mt < 4; mt++)
        #pragma unroll
        for (int nt = 0; nt < 4; nt++){
            int r = mrow + mt*16, cc = ncol + nt*8;
            #pragma unroll
            for (int hrow = 0; hrow < 2; hrow++){
                float v0 = acc[mt][nt][2*hrow], v1 = acc[mt][nt][2*hrow+1];
                uint32_t hp = pack_bf2(v0, v1);
                uint32_t lp = pack_bf2(v0 - __uint_as_float(hp << 16),
                                       v1 - __uint_as_float(hp & 0xFFFF0000u));
                size_t o = (size_t)(r + 8*hrow)*2048 + cc;
                *(uint32_t*)&g_wch[o] = hp;
                *(uint32_t*)&g_wcl[o] = lp;
            }
        }
}
__global__ __launch_bounds__(512, 1) void gemm3_tc(
    const __grid_constant__ CUtensorMap tAh, const __grid_constant__ CUtensorMap tAl,
    const __grid_constant__ CUtensorMap tBh, const __grid_constant__ CUtensorMap tBl,
    const float* __restrict__ b_dt, int row0){
    float acc[4][4][4] = {};
    gemm_core_v4<256,2>(&tAh,&tAl,&tBh,&tBl, row0 + blockIdx.y*128, blockIdx.x*256, DINNER, acc);
    EPI3_SETUP(256, 2, row0);
    #pragma unroll
    for (int mt = 0; mt < 4; mt++)
        #pragma unroll
        for (int nt = 0; nt < 4; nt++){
            int r = mrow + mt*16, cc = ncol + nt*8;
            float b0 = b_dt[cc], b1 = b_dt[cc+1];
            g_dt[(size_t)r*DINNER + cc]       = softplus_f(acc[mt][nt][0] + b0);
            g_dt[(size_t)r*DINNER + cc + 1]   = softplus_f(acc[mt][nt][1] + b1);
            g_dt[(size_t)(r+8)*DINNER + cc]   = softplus_f(acc[mt][nt][2] + b0);
            g_dt[(size_t)(r+8)*DINNER + cc+1] = softplus_f(acc[mt][nt][3] + b1);
        }
}
__global__ __launch_bounds__(512, 1) void gemm4_tc(
    const __grid_constant__ CUtensorMap tAh, const __grid_constant__ CUtensorMap tAl,
    const __grid_constant__ CUtensorMap tBh, const __grid_constant__ CUtensorMap tBl,
    float* __restrict__ out, int row0){
    float acc[4][4][4] = {};
    gemm_core_v4<256,2>(&tAh,&tAl,&tBh,&tBl, row0 + blockIdx.y*128, blockIdx.x*256, DINNER, acc);
    EPI3_SETUP(256, 2, row0);
    #pragma unroll
    for (int mt = 0; mt < 4; mt++)
        #pragma unroll
        for (int nt = 0; nt < 4; nt++){
            int r = mrow + mt*16, cc = ncol + nt*8;
            *(float2*)&out[(size_t)r*DMODEL + cc]     = make_float2(acc[mt][nt][0], acc[mt][nt][1]);
            *(float2*)&out[(size_t)(r+8)*DMODEL + cc] = make_float2(acc[mt][nt][2], acc[mt][nt][3]);
        }
}

// ---------------- prep ----------------
__global__ __launch_bounds__(256) void split_x_kernel(const float* __restrict__ x){
    int idx = blockIdx.x*256 + threadIdx.x;
    float v = x[idx];
    __nv_bfloat16 h = __float2bfloat16(v);
    g_xh[idx] = h;
    g_xl[idx] = __float2bfloat16(v - __bfloat162float(h));
}
__global__ __launch_bounds__(256) void wsplit_kernel(const float* __restrict__ W,
                                                     __nv_bfloat16* __restrict__ oh,
                                                     __nv_bfloat16* __restrict__ ol,
                                                     int K, int N){
    __shared__ float tl[32][33];
    const int n0 = blockIdx.x*32, k0 = blockIdx.y*32;
    const int tx = threadIdx.x & 31, ty = threadIdx.x >> 5;
    #pragma unroll
    for (int i = 0; i < 4; i++)
        tl[ty + i*8][tx] = W[(size_t)(k0 + ty + i*8)*N + n0 + tx];
    __syncthreads();
    #pragma unroll
    for (int i = 0; i < 4; i++){
        int nl = ty + i*8;
        float v = tl[tx][nl];
        __nv_bfloat16 h = __float2bfloat16(v);
        size_t o = (size_t)(n0 + nl)*K + k0 + tx;
        oh[o] = h;
        ol[o] = __float2bfloat16(v - __bfloat162float(h));
    }
}
__global__ __launch_bounds__(256) void wsplit_direct(const float* __restrict__ W,
                                                     __nv_bfloat16* __restrict__ oh,
                                                     __nv_bfloat16* __restrict__ ol,
                                                     int ldw, int coloff, int JCOLS){
    int idx = blockIdx.x*256 + threadIdx.x;
    int k = idx / JCOLS, j = idx - k*JCOLS;
    float v = W[(size_t)k*ldw + coloff + j];
    __nv_bfloat16 h = __float2bfloat16(v);
    oh[idx] = h;
    ol[idx] = __float2bfloat16(v - __bfloat162float(h));
}

// ---------------- conv + SiLU ----------------
__global__ __launch_bounds__(256) void conv_silu_kernel(const float* __restrict__ cw,
                                                        const float* __restrict__ cb){
    int idx = blockIdx.x*256 + threadIdx.x;
    int d   = idx & (DINNER - 1);
    int row = idx >> 11;
    int t   = row & (LL - 1);
    float acc = cb[d];
    #pragma unroll
    for (int k = 0; k < DCONV; k++){
        int tt = t - (DCONV - 1) + k;
        if (tt >= 0)
            acc = fmaf(g_xz[(size_t)(row - (DCONV - 1) + k)*(2*DINNER) + d], cw[d*DCONV + k], acc);
    }
    float v = silu_f(acc);
    g_xc[idx] = v;
    __nv_bfloat16 h = __float2bfloat16(v);
    g_xch[idx] = h;
    g_xcl[idx] = __float2bfloat16(v - __bfloat162float(h));
}

// ---------------- scan (per-batch kernels) ----------------
__global__ __launch_bounds__(256) void scan_phase1(const float* __restrict__ A_log, int b){
    const int blk = blockIdx.x;              // 0..511
    const int dgrp = blk & 15, chunk = blk >> 4;
    const int tid = threadIdx.x, dloc = tid >> 1, half = tid & 1;
    const int d = dgrp*128 + dloc, s0 = half*32;
    const float u = -expf(A_log[d*DSTATE]) * LOG2E;
    float a2[32], h[32];
    bool fast = true;
    #pragma unroll
    for (int i = 0; i < 32; i++){
        a2[i] = -expf(A_log[d*DSTATE + s0 + i]) * LOG2E;
        float ex = u * (float)(s0 + i + 1);
        fast = fast && (fabsf(a2[i] - ex) <= 1e-6f*fabsf(ex) + 1e-30f);
        h[i] = 0.f;
    }
    __shared__ float sBC[2][128];
    const int rowbase = b*LL + chunk*CHUNK;
    float sdt = 0.f;
    for (int t = 0; t < CHUNK; t++){
        const int row = rowbase + t;
        if (tid < 128) sBC[t & 1][tid] = g_bc[(size_t)row*128 + tid];
        __syncthreads();
        const float dtv = g_dt[(size_t)row*DINNER + d];
        const float uv  = dtv * g_xc[(size_t)row*DINNER + d];
        const float* Bv = &sBC[t & 1][s0];
        sdt += dtv;
        if (fast){
            float q = ex2f(dtv * u);
            float q2=q*q, q4=q2*q2, q8=q4*q4, q16=q8*q8;
            float dA0;
            if (s0 == 0) dA0 = q;
            else { float q32=q16*q16; dA0 = q32*q; }
            float dA1 = dA0*q16;
            #pragma unroll
            for (int i = 0; i < 16; i++){
                h[i]    = fmaf(dA0, h[i],    uv * Bv[i]);
                h[i+16] = fmaf(dA1, h[i+16], uv * Bv[i+16]);
                dA0 *= q; dA1 *= q;
            }
        } else {
            #pragma unroll
            for (int i = 0; i < 32; i++){
                float dA = ex2f(dtv * a2[i]);
                h[i] = fmaf(dA, h[i], uv * Bv[i]);
            }
        }
    }
    // P[s] = exp(A_s * sum dt) computed once per chunk
    float p[32];
    if (fast){
        float qp = ex2f(sdt * u);
        float p2=qp*qp, p4=p2*p2, p8=p4*p4, p16=p8*p8;
        float dP0;
        if (s0 == 0) dP0 = qp;
        else { float p32=p16*p16; dP0 = p32*qp; }
        float dP1 = dP0*p16;
        #pragma unroll
        for (int i = 0; i < 16; i++){
            p[i] = dP0; p[i+16] = dP1;
            dP0 *= qp; dP1 *= qp;
        }
    } else {
        #pragma unroll
        for (int i = 0; i < 32; i++) p[i] = ex2f(a2[i] * sdt);
    }
    const int base = ((b*NCHUNK + chunk)*DSTATE + s0)*DINNER + d;
    #pragma unroll
    for (int i = 0; i < 32; i++){ g_E[base + i*DINNER] = h[i]; g_P[base + i*DINNER] = p[i]; }
}
__global__ __launch_bounds__(256) void scan_combine(int b){
    const int idx = blockIdx.x*256 + threadIdx.x;     // 0..131071
    const int d = idx & (DINNER-1), s = idx >> 11;
    float h = 0.f;
    for (int j = 0; j < NCHUNK; j++){
        const int o = ((b*NCHUNK + j)*DSTATE + s)*DINNER + d;
        g_hin[o] = h;
        h = fmaf(g_P[o], h, g_E[o]);
    }
}
__global__ __launch_bounds__(256) void scan_phase3(const float* __restrict__ A_log,
                                                   const float* __restrict__ D_param, int b){
    const int blk = blockIdx.x;
    const int dgrp = blk & 15, chunk = blk >> 4;
    const int tid = threadIdx.x, dloc = tid >> 1, half = tid & 1;
    const int d = dgrp*128 + dloc, s0 = half*32;
    const float u = -expf(A_log[d*DSTATE]) * LOG2E;
    float a2[32], h[32];
    bool fast = true;
    const int hbase = ((b*NCHUNK + chunk)*DSTATE + s0)*DINNER + d;
    #pragma unroll
    for (int i = 0; i < 32; i++){
        a2[i] = -expf(A_log[d*DSTATE + s0 + i]) * LOG2E;
        float ex = u * (float)(s0 + i + 1);
        fast = fast && (fabsf(a2[i] - ex) <= 1e-6f*fabsf(ex) + 1e-30f);
        h[i]  = g_hin[hbase + i*DINNER];
    }
    const float Dv = D_param[d];
    __shared__ float sBC[2][128];
    const int rowbase = b*LL + chunk*CHUNK;
    for (int t = 0; t < CHUNK; t++){
        const int row = rowbase + t;
        if (tid < 128) sBC[t & 1][tid] = g_bc[(size_t)row*128 + tid];
        __syncthreads();
        const float dtv = g_dt[(size_t)row*DINNER + d];
        const float xcv = g_xc[(size_t)row*DINNER + d];
        const float uv  = dtv * xcv;
        const float* Bv = &sBC[t & 1][s0];
        const float* Cv = &sBC[t & 1][64 + s0];
        float yacc = 0.f;
        if (fast){
            float q = ex2f(dtv * u);
            float q2=q*q, q4=q2*q2, q8=q4*q4, q16=q8*q8;
            float dA0;
            if (s0 == 0) dA0 = q;
            else { float q32=q16*q16; dA0 = q32*q; }
            float dA1 = dA0*q16;
            #pragma unroll
            for (int i = 0; i < 16; i++){
                h[i]    = fmaf(dA0, h[i],    uv * Bv[i]);
                yacc    = fmaf(h[i],    Cv[i],    yacc);
                h[i+16] = fmaf(dA1, h[i+16], uv * Bv[i+16]);
                yacc    = fmaf(h[i+16], Cv[i+16], yacc);
                dA0 *= q; dA1 *= q;
            }
        } else {
            #pragma unroll
            for (int i = 0; i < 32; i++){
                float dA = ex2f(dtv * a2[i]);
                h[i] = fmaf(dA, h[i], uv * Bv[i]);
                yacc = fmaf(h[i], Cv[i], yacc);
            }
        }
        yacc += __shfl_xor_sync(0xffffffffu, yacc, 1);
        if (half == 0){
            const size_t o = (size_t)row*DINNER + d;
            g_y[o] = yacc + Dv * xcv;
        }
    }
}

// ---------------- RMSNorm + silu(z) gate -> split bf16 ----------------
__global__ __launch_bounds__(256) void norm_kernel(const float* __restrict__ norm_w, int row0){
    const int row = row0 + blockIdx.x, tid = threadIdx.x;
    const size_t base = (size_t)row*DINNER;
    float ss = 0.f;
    for (int i = tid; i < DINNER; i += 256){
        float v = g_y[base + i];
        ss = fmaf(v, v, ss);
    }
    #pragma unroll
    for (int o = 16; o; o >>= 1) ss += __shfl_xor_sync(0xffffffffu, ss, o);
    __shared__ float red[8];
    __shared__ float s_inv;
    if ((tid & 31) == 0) red[tid >> 5] = ss;
    __syncthreads();
    if (tid == 0){
        float t = 0.f;
        #pragma unroll
        for (int i = 0; i < 8; i++) t += red[i];
        s_inv = rsqrtf(t/(float)DINNER + EPSV);
    }
    __syncthreads();
    const float inv = s_inv;
    for (int i = tid; i < DINNER; i += 256){
        float v  = g_y[base + i]*inv*norm_w[i];
        float zv = g_xz[(size_t)row*(2*DINNER) + DINNER + i];
        float yv = v*silu_f(zv);
        __nv_bfloat16 h = __float2bfloat16(yv);
        g_ynh[base + i] = h;
        g_ynl[base + i] = __float2bfloat16(yv - __bfloat162float(h));
    }
}

// ---------------- host-side tensormap builder (dlopen, no -lcuda) ----------
typedef CUresult (*EncFn)(CUtensorMap*, CUtensorMapDataType, cuuint32_t, void*,
    const cuuint64_t*, const cuuint64_t*, const cuuint32_t*, const cuuint32_t*,
    CUtensorMapInterleave, CUtensorMapSwizzle, CUtensorMapL2promotion, CUtensorMapFloatOOBfill);

static EncFn get_enc(){
    void* h = dlopen("libcuda.so.1", RTLD_LAZY | RTLD_GLOBAL);
    if (!h) h = dlopen("libcuda.so", RTLD_LAZY | RTLD_GLOBAL);
    if (!h) return nullptr;
    return (EncFn)dlsym(h, "cuTensorMapEncodeTiled");
}
static void mkmap(EncFn f, CUtensorMap* m, void* p, uint64_t K, uint64_t R, uint32_t boxR){
    if (!f || !p) return;
    cuuint64_t gd[2] = {K, R};
    cuuint64_t gs[1] = {K*2};
    cuuint32_t bd[2] = {64, boxR};
    cuuint32_t es[2] = {1, 1};
    f(m, CU_TENSOR_MAP_DATA_TYPE_BFLOAT16, 2, p, gd, gs, bd, es,
      CU_TENSOR_MAP_INTERLEAVE_NONE, CU_TENSOR_MAP_SWIZZLE_128B,
      CU_TENSOR_MAP_L2_PROMOTION_L2_128B, CU_TENSOR_MAP_FLOAT_OOB_FILL_NONE);
}

// ---------------- launch ----------------
extern "C" void kernel_launch(void* const* d_in, const int* in_sizes, int n_in,
                              void* d_out, int out_size){
    const float* x      = (const float*)d_in[0];
    const float* W_in   = (const float*)d_in[1];
    const float* conv_w = (const float*)d_in[2];
    const float* conv_b = (const float*)d_in[3];
    const float* W_x    = (const float*)d_in[4];
    const float* W_dt   = (const float*)d_in[5];
    const float* b_dt   = (const float*)d_in[6];
    const float* A_log  = (const float*)d_in[7];
    const float* D_par  = (const float*)d_in[8];
    const float* W_out  = (const float*)d_in[9];
    const float* norm_w = (const float*)d_in[10];
    float* out = (float*)d_out;

    const int STG256 = 32768 + 256*256;
    const int STG128 = 32768 + 128*256;
    const int SM256  = 2*STG256 + 1024 + 64;
    const int SM128  = 2*STG128 + 1024 + 64;
    cudaFuncSetAttribute(gemm1_tc,   cudaFuncAttributeMaxDynamicSharedMemorySize, SM256);
    cudaFuncSetAttribute(gemm2a_tc,  cudaFuncAttributeMaxDynamicSharedMemorySize, SM128);
    cudaFuncSetAttribute(wcombine_tc,cudaFuncAttributeMaxDynamicSharedMemorySize, SM256);
    cudaFuncSetAttribute(gemm3_tc,   cudaFuncAttributeMaxDynamicSharedMemorySize, SM256);
    cudaFuncSetAttribute(gemm4_tc,   cudaFuncAttributeMaxDynamicSharedMemorySize, SM256);

    void *xh,*xl,*xch,*xcl,*ynh,*ynl,*winh,*winl,*wxh,*wxl,*wdth,*wdtl,*wouth,*woutl,*wx2h,*wx2l,*wch,*wcl;
    cudaGetSymbolAddress(&xh,  g_xh);   cudaGetSymbolAddress(&xl,  g_xl);
    cudaGetSymbolAddress(&xch, g_xch);  cudaGetSymbolAddress(&xcl, g_xcl);
    cudaGetSymbolAddress(&ynh, g_ynh);  cudaGetSymbolAddress(&ynl, g_ynl);
    cudaGetSymbolAddress(&winh,g_winh); cudaGetSymbolAddress(&winl,g_winl);
    cudaGetSymbolAddress(&wxh, g_wxh);  cudaGetSymbolAddress(&wxl, g_wxl);
    cudaGetSymbolAddress(&wdth,g_wdth); cudaGetSymbolAddress(&wdtl,g_wdtl);
    cudaGetSymbolAddress(&wouth,g_wouth);cudaGetSymbolAddress(&woutl,g_woutl);
    cudaGetSymbolAddress(&wx2h,g_wx2h); cudaGetSymbolAddress(&wx2l,g_wx2l);
    cudaGetSymbolAddress(&wch, g_wch);  cudaGetSymbolAddress(&wcl, g_wcl);

    static EncFn enc = nullptr;
    if (!enc) enc = get_enc();
    static CUtensorMap m_xh, m_xl, m_xch, m_xcl, m_ynh, m_ynl;
    static CUtensorMap m_winh, m_winl, m_wxh, m_wxl, m_wdth, m_wdtl;
    static CUtensorMap m_wouth, m_woutl, m_wx2h, m_wx2l, m_wch, m_wcl;
    mkmap(enc, &m_xh,   xh,   1024, ROWS, 128);
    mkmap(enc, &m_xl,   xl,   1024, ROWS, 128);
    mkmap(enc, &m_xch,  xch,  2048, ROWS, 128);
    mkmap(enc, &m_xcl,  xcl,  2048, ROWS, 128);
    mkmap(enc, &m_ynh,  ynh,  2048, ROWS, 128);
    mkmap(enc, &m_ynl,  ynl,  2048, ROWS, 128);
    mkmap(enc, &m_winh, winh, 1024, 4096, 256);
    mkmap(enc, &m_winl, winl, 1024, 4096, 256);
    mkmap(enc, &m_wxh,  wxh,  2048, 128,  128);
    mkmap(enc, &m_wxl,  wxl,  2048, 128,  128);
    mkmap(enc, &m_wdth, wdth, 2048, 2048, 128);
    mkmap(enc, &m_wdtl, wdtl, 2048, 2048, 128);
    mkmap(enc, &m_wouth,wouth,2048, 1024, 256);
    mkmap(enc, &m_woutl,woutl,2048, 1024, 256);
    mkmap(enc, &m_wx2h, wx2h, 2048, 2048, 256);
    mkmap(enc, &m_wx2l, wx2l, 2048, 2048, 256);
    mkmap(enc, &m_wch,  wch,  2048, 2048, 256);
    mkmap(enc, &m_wcl,  wcl,  2048, 2048, 256);

    static cudaStream_t sB = nullptr;
    static cudaEvent_t evF1, evJ1, evC, ev3a, evDone;
    if (!sB){
        cudaStreamCreateWithFlags(&sB, cudaStreamNonBlocking);
        cudaEventCreateWithFlags(&evF1,  cudaEventDisableTiming);
        cudaEventCreateWithFlags(&evJ1,  cudaEventDisableTiming);
        cudaEventCreateWithFlags(&evC,   cudaEventDisableTiming);
        cudaEventCreateWithFlags(&ev3a,  cudaEventDisableTiming);
        cudaEventCreateWithFlags(&evDone,cudaEventDisableTiming);
    }

    // s0: gemm1 deps
    split_x_kernel<<<(ROWS*DMODEL)/256, 256>>>(x);
    wsplit_kernel<<<dim3(4096/32, 1024/32), 256>>>(W_in,  (__nv_bfloat16*)winh, (__nv_bfloat16*)winl, 1024, 4096);
    cudaEventRecord(evF1, 0);

    // sB: weight prep + wcombine (overlaps gemm1)
    cudaStreamWaitEvent(sB, evF1, 0);
    wsplit_kernel<<<dim3(128/32,  2048/32), 256, 0, sB>>>(W_x,   (__nv_bfloat16*)wxh,  (__nv_bfloat16*)wxl,  2048, 2176);
    wsplit_kernel<<<dim3(2048/32, 2048/32), 256, 0, sB>>>(W_dt,  (__nv_bfloat16*)wdth, (__nv_bfloat16*)wdtl, 2048, 2048);
    wsplit_kernel<<<dim3(1024/32, 2048/32), 256, 0, sB>>>(W_out, (__nv_bfloat16*)wouth,(__nv_bfloat16*)woutl,2048, 1024);
    wsplit_direct<<<(2048*2048)/256, 256, 0, sB>>>(W_x, (__nv_bfloat16*)wx2h, (__nv_bfloat16*)wx2l, 2176, 128, 2048);
    wcombine_tc<<<dim3(8, 16), 512, SM256, sB>>>(m_wdth, m_wdtl, m_wx2h, m_wx2l);
    cudaEventRecord(evJ1, sB);

    // s0: gemm1, conv
    gemm1_tc<<<dim3(16, 64), 512, SM256>>>(m_xh, m_xl, m_winh, m_winl);
    conv_silu_kernel<<<(ROWS*DINNER)/256, 256>>>(conv_w, conv_b);
    cudaEventRecord(evC, 0);
    cudaStreamWaitEvent(0, evJ1, 0);

    // --- batch-0 chain on s0 ---
    gemm2a_tc<<<dim3(1, 32), 512, SM128>>>(m_xch, m_xcl, m_wxh, m_wxl, 0);
    gemm3_tc<<<dim3(8, 32), 512, SM256>>>(m_xch, m_xcl, m_wch, m_wcl, b_dt, 0);
    cudaEventRecord(ev3a, 0);
    scan_phase1<<<NCHUNK*(DINNER/128), 256>>>(A_log, 0);
    scan_combine<<<(DSTATE*DINNER)/256, 256>>>(0);
    scan_phase3<<<NCHUNK*(DINNER/128), 256>>>(A_log, D_par, 0);
    norm_kernel<<<LL, 256>>>(norm_w, 0);
    gemm4_tc<<<dim3(4, 32), 512, SM256>>>(m_ynh, m_ynl, m_wouth, m_woutl, out, 0);

    // --- batch-1 chain on sB (gemm3_b1 ordered after gemm3_b0; overlaps b0 scan) ---
    cudaStreamWaitEvent(sB, evC, 0);
    gemm2a_tc<<<dim3(1, 32), 512, SM128, sB>>>(m_xch, m_xcl, m_wxh, m_wxl, LL);
    cudaStreamWaitEvent(sB, ev3a, 0);
    gemm3_tc<<<dim3(8, 32), 512, SM256, sB>>>(m_xch, m_xcl, m_wch, m_wcl, b_dt, LL);
    scan_phase1<<<NCHUNK*(DINNER/128), 256, 0, sB>>>(A_log, 1);
    scan_combine<<<(DSTATE*DINNER)/256, 256, 0, sB>>>(1);
    scan_phase3<<<NCHUNK*(DINNER/128), 256, 0, sB>>>(A_log, D_par, 1);
    norm_kernel<<<LL, 256, 0, sB>>>(norm_w, LL);
    gemm4_tc<<<dim3(4, 32), 512, SM256, sB>>>(m_ynh, m_ynl, m_wouth, m_woutl, out, LL);
    cudaEventRecord(evDone, sB);

    // join
    cudaStreamWaitEvent(0, evDone, 0);
}

// round 16
// speedup vs baseline: 1.2520x; 1.0123x over previous
#include <cuda_runtime.h>
#include <cuda.h>
#include <cuda_bf16.h>
#include <math.h>
#include <stdint.h>
#include <dlfcn.h>

#define BB     2
#define LL     4096
#define DMODEL 1024
#define DSTATE 64
#define DCONV  4
#define DINNER 2048
#define ROWS   (BB*LL)
#define EPSV   1.1920929e-07f
#define CHUNK  128
#define NCHUNK (LL/CHUNK)
#define LOG2E  1.44269504088896340736f

// ---------------- scratch ----------------
__device__ __align__(128) float g_xz [ROWS * (2*DINNER)];
__device__ __align__(128) float g_xc [ROWS * DINNER];
__device__ __align__(128) float g_bc [ROWS * 128];
__device__ __align__(128) float g_dt [ROWS * DINNER];
__device__ __align__(128) float g_y  [ROWS * DINNER];
__device__ __align__(128) float g_E  [BB*NCHUNK*DSTATE*DINNER];
__device__ __align__(128) float g_P  [BB*NCHUNK*DSTATE*DINNER];
__device__ __align__(128) float g_hin[BB*NCHUNK*DSTATE*DINNER];
__device__ __align__(128) __nv_bfloat16 g_xh  [ROWS*DMODEL], g_xl  [ROWS*DMODEL];
__device__ __align__(128) __nv_bfloat16 g_xch [ROWS*DINNER], g_xcl [ROWS*DINNER];
__device__ __align__(128) __nv_bfloat16 g_ynh [ROWS*DINNER], g_ynl [ROWS*DINNER];
__device__ __align__(128) __nv_bfloat16 g_winh [4096*1024], g_winl [4096*1024];
__device__ __align__(128) __nv_bfloat16 g_wxh  [128*2048],  g_wxl  [128*2048];
__device__ __align__(128) __nv_bfloat16 g_wdth [2048*2048], g_wdtl [2048*2048];
__device__ __align__(128) __nv_bfloat16 g_wouth[1024*2048], g_woutl[1024*2048];
__device__ __align__(128) __nv_bfloat16 g_wx2h [2048*2048], g_wx2l [2048*2048];
__device__ __align__(128) __nv_bfloat16 g_wch  [2048*2048], g_wcl  [2048*2048];

// ---------------- device helpers ----------------
__device__ __forceinline__ float ex2f(float x){ float y; asm("ex2.approx.ftz.f32 %0, %1;":"=f"(y):"f"(x)); return y; }
__device__ __forceinline__ float softplus_f(float x){ return x > 20.f ? x : log1pf(expf(x)); }
__device__ __forceinline__ float silu_f(float x){ return x / (1.f + expf(-x)); }
__device__ __forceinline__ uint32_t pack_bf2(float lo, float hi){
    uint32_t r; asm("cvt.rn.bf16x2.f32 %0, %1, %2;":"=r"(r):"f"(hi),"f"(lo)); return r;
}
__device__ __forceinline__ uint32_t smem_u32(const void* p){
    uint32_t a; asm("{ .reg .u64 t; cvta.to.shared.u64 t, %1; cvt.u32.u64 %0, t; }":"=r"(a):"l"(p)); return a;
}
__device__ __forceinline__ void mma_bf16(float (&d)[4], const uint32_t* a, const uint32_t* b){
    asm volatile("mma.sync.aligned.m16n8k16.row.col.f32.bf16.bf16.f32 "
        "{%0,%1,%2,%3}, {%4,%5,%6,%7}, {%8,%9}, {%0,%1,%2,%3};"
        : "+f"(d[0]), "+f"(d[1]), "+f"(d[2]), "+f"(d[3])
        : "r"(a[0]), "r"(a[1]), "r"(a[2]), "r"(a[3]), "r"(b[0]), "r"(b[1]));
}
__device__ __forceinline__ void ldsm4(uint32_t* r, uint32_t addr){
    asm volatile("ldmatrix.sync.aligned.m8n8.x4.shared.b16 {%0,%1,%2,%3}, [%4];"
        : "=r"(r[0]), "=r"(r[1]), "=r"(r[2]), "=r"(r[3]) : "r"(addr));
}
__device__ __forceinline__ void mbar_init(uint32_t a, uint32_t c){
    asm volatile("mbarrier.init.shared.b64 [%0], %1;"::"r"(a),"r"(c):"memory");
}
__device__ __forceinline__ void mbar_wait(uint32_t a, uint32_t par){
    asm volatile("{\n\t.reg .pred P;\n\tW_%=:\n\t"
        "mbarrier.try_wait.parity.acquire.cta.shared::cta.b64 P, [%0], %1, 0x989680;\n\t"
        "@P bra.uni D_%=;\n\tbra.uni W_%=;\n\tD_%=:\n\t}"::"r"(a),"r"(par):"memory");
}
__device__ __forceinline__ void tma2d(uint32_t smem, const CUtensorMap* m, int x, int y, uint32_t mb){
    asm volatile("cp.async.bulk.tensor.2d.shared::cta.global.tile.mbarrier::complete_tx::bytes "
        "[%0], [%1, {%2, %3}], [%4];" :: "r"(smem), "l"(m), "r"(x), "r"(y), "r"(mb) : "memory");
}
__device__ __forceinline__ uint32_t swz128(uint32_t off){ return off ^ ((off >> 3) & 0x70); }

// ---------------- TMA-fed HMMA bf16x3 core: 128 x NT tile, BK=64, 512 thr ----
template<int NT, int NG>   // NG = NT/128
__device__ __forceinline__ void gemm_core_v4(
    const CUtensorMap* tAh, const CUtensorMap* tAl,
    const CUtensorMap* tBh, const CUtensorMap* tBl,
    int rowA, int rowB, int ktot, float (&acc)[4][2*NG][4])
{
    constexpr int STG = 32768 + NT*256;
    extern __shared__ __align__(1024) char smbuf[];
    const uint32_t sm  = (smem_u32(smbuf) + 1023u) & ~1023u;
    const uint32_t mb0 = sm + 2u*STG;
    const int t = threadIdx.x, lane = t & 31, wid = t >> 5;
    const int m0 = (wid & 1)*64, n0 = (wid >> 1)*(16*NG);
    const int lr = lane & 15, lc = lane >> 4;
    const int kch = ktot >> 6;

    if (t == 0){ mbar_init(mb0, 1); mbar_init(mb0 + 8, 1); }
    __syncthreads();

    auto issue = [&](int c, int s){
        if (t == 0){
            const uint32_t mb = mb0 + (uint32_t)s*8u;
            asm volatile("mbarrier.arrive.expect_tx.shared.b64 _, [%0], %1;"
                         :: "r"(mb), "r"((uint32_t)STG) : "memory");
            const uint32_t base = sm + (uint32_t)s*STG;
            const int kx = c*64;
            tma2d(base,                  tAh, kx, rowA, mb);
            tma2d(base + 16384,          tAl, kx, rowA, mb);
            tma2d(base + 32768,          tBh, kx, rowB, mb);
            tma2d(base + 32768 + NT*128, tBl, kx, rowB, mb);
        }
    };
    issue(0, 0);
    issue(1, 1);
    uint32_t ph[2] = {0u, 0u};

    for (int c = 0; c < kch; c++){
        const int s = c & 1;
        mbar_wait(mb0 + (uint32_t)s*8u, ph[s]); ph[s] ^= 1u;
        const uint32_t base = sm + (uint32_t)s*STG;
        #pragma unroll
        for (int ks = 0; ks < 4; ks++){
            const int ch = ks*2 + lc;
            uint32_t bh[NG][4], bl[NG][4];
            #pragma unroll
            for (int g = 0; g < NG; g++){
                uint32_t a = base + 32768 + swz128((uint32_t)((n0 + g*16 + lr)*128 + ch*16));
                ldsm4(bh[g], a);
                ldsm4(bl[g], a + NT*128);
            }
            #pragma unroll
            for (int mt = 0; mt < 4; mt++){
                uint32_t a = base + swz128((uint32_t)((m0 + mt*16 + lr)*128 + ch*16));
                uint32_t ah[4], al[4];
                ldsm4(ah, a);
                ldsm4(al, a + 16384);
                #pragma unroll
                for (int nt = 0; nt < 2*NG; nt++){
                    const int g = nt >> 1, sel = nt & 1;
                    uint32_t bfh[2] = { bh[g][sel], bh[g][sel+2] };
                    uint32_t bfl[2] = { bl[g][sel], bl[g][sel+2] };
                    mma_bf16(acc[mt][nt], ah, bfh);
                    mma_bf16(acc[mt][nt], al, bfh);
                    mma_bf16(acc[mt][nt], ah, bfl);
                }
            }
        }
        __syncthreads();
        if (c + 2 < kch) issue(c + 2, s);
    }
}

#define EPI3_SETUP(NT, NG, RO) \
    const int lane = threadIdx.x & 31; \
    const int wid  = threadIdx.x >> 5; \
    const int mrow = (RO) + blockIdx.y * 128 + (wid & 1) * 64 + (lane >> 2); \
    const int ncol = blockIdx.x * NT + (wid >> 1) * (16*NG) + (lane & 3) * 2;

// ---------------- GEMM kernels ----------------
__global__ __launch_bounds__(512, 1) void gemm1_tc(
    const __grid_constant__ CUtensorMap tAh, const __grid_constant__ CUtensorMap tAl,
    const __grid_constant__ CUtensorMap tBh, const __grid_constant__ CUtensorMap tBl,
    int row0){
    float acc[4][4][4] = {};
    gemm_core_v4<256,2>(&tAh,&tAl,&tBh,&tBl, row0 + blockIdx.y*128, blockIdx.x*256, DMODEL, acc);
    EPI3_SETUP(256, 2, row0);
    #pragma unroll
    for (int mt = 0; mt < 4; mt++)
        #pragma unroll
        for (int nt = 0; nt < 4; nt++){
            int r = mrow + mt*16, cc = ncol + nt*8;
            *(float2*)&g_xz[(size_t)r*(2*DINNER) + cc]     = make_float2(acc[mt][nt][0], acc[mt][nt][1]);
            *(float2*)&g_xz[(size_t)(r+8)*(2*DINNER) + cc] = make_float2(acc[mt][nt][2], acc[mt][nt][3]);
        }
}
__global__ __launch_bounds__(512, 1) void gemm2a_tc(
    const __grid_constant__ CUtensorMap tAh, const __grid_constant__ CUtensorMap tAl,
    const __grid_constant__ CUtensorMap tBh, const __grid_constant__ CUtensorMap tBl,
    int row0){
    float acc[4][2][4] = {};
    gemm_core_v4<128,1>(&tAh,&tAl,&tBh,&tBl, row0 + blockIdx.y*128, 0, DINNER, acc);
    EPI3_SETUP(128, 1, row0);
    #pragma unroll
    for (int mt = 0; mt < 4; mt++)
        #pragma unroll
        for (int nt = 0; nt < 2; nt++){
            int r = mrow + mt*16, cc = ncol + nt*8;
            *(float2*)&g_bc[(size_t)r*128 + cc]     = make_float2(acc[mt][nt][0], acc[mt][nt][1]);
            *(float2*)&g_bc[(size_t)(r+8)*128 + cc] = make_float2(acc[mt][nt][2], acc[mt][nt][3]);
        }
}
__global__ __launch_bounds__(512, 1) void wcombine_tc(
    const __grid_constant__ CUtensorMap tAh, const __grid_constant__ CUtensorMap tAl,
    const __grid_constant__ CUtensorMap tBh, const __grid_constant__ CUtensorMap tBl){
    float acc[4][4][4] = {};
    gemm_core_v4<256,2>(&tAh,&tAl,&tBh,&tBl, blockIdx.y*128, blockIdx.x*256, 2048, acc);
    EPI3_SETUP(256, 2, 0);
    #pragma unroll
    for (int mt = 0; mt < 4; mt++)
        #pragma unroll
        for (int nt = 0; nt < 4; nt++){
            int r = mrow + mt*16, cc = ncol + nt*8;
            #pragma unroll
            for (int hrow = 0; hrow < 2; hrow++){
                float v0 = acc[mt][nt][2*hrow], v1 = acc[mt][nt][2*hrow+1];
                uint32_t hp = pack_bf2(v0, v1);
                uint32_t lp = pack_bf2(v0 - __uint_as_float(hp << 16),
                                       v1 - __uint_as_float(hp & 0xFFFF0000u));
                size_t o = (size_t)(r + 8*hrow)*2048 + cc;
                *(uint32_t*)&g_wch[o] = hp;
                *(uint32_t*)&g_wcl[o] = lp;
            }
        }
}
__global__ __launch_bounds__(512, 1) void gemm3_tc(
    const __grid_constant__ CUtensorMap tAh, const __grid_constant__ CUtensorMap tAl,
    const __grid_constant__ CUtensorMap tBh, const __grid_constant__ CUtensorMap tBl,
    const float* __restrict__ b_dt, int row0){
    float acc[4][4][4] = {};
    gemm_core_v4<256,2>(&tAh,&tAl,&tBh,&tBl, row0 + blockIdx.y*128, blockIdx.x*256, DINNER, acc);
    EPI3_SETUP(256, 2, row0);
    #pragma unroll
    for (int mt = 0; mt < 4; mt++)
        #pragma unroll
        for (int nt = 0; nt < 4; nt++){
            int r = mrow + mt*16, cc = ncol + nt*8;
            float b0 = b_dt[cc], b1 = b_dt[cc+1];
            g_dt[(size_t)r*DINNER + cc]       = softplus_f(acc[mt][nt][0] + b0);
            g_dt[(size_t)r*DINNER + cc + 1]   = softplus_f(acc[mt][nt][1] + b1);
            g_dt[(size_t)(r+8)*DINNER + cc]   = softplus_f(acc[mt][nt][2] + b0);
            g_dt[(size_t)(r+8)*DINNER + cc+1] = softplus_f(acc[mt][nt][3] + b1);
        }
}
__global__ __launch_bounds__(512, 1) void gemm4_tc(
    const __grid_constant__ CUtensorMap tAh, const __grid_constant__ CUtensorMap tAl,
    const __grid_constant__ CUtensorMap tBh, const __grid_constant__ CUtensorMap tBl,
    float* __restrict__ out, int row0){
    float acc[4][4][4] = {};
    gemm_core_v4<256,2>(&tAh,&tAl,&tBh,&tBl, row0 + blockIdx.y*128, blockIdx.x*256, DINNER, acc);
    EPI3_SETUP(256, 2, row0);
    #pragma unroll
    for (int mt = 0; mt < 4; mt++)
        #pragma unroll
        for (int nt = 0; nt < 4; nt++){
            int r = mrow + mt*16, cc = ncol + nt*8;
            *(float2*)&out[(size_t)r*DMODEL + cc]     = make_float2(acc[mt][nt][0], acc[mt][nt][1]);
            *(float2*)&out[(size_t)(r+8)*DMODEL + cc] = make_float2(acc[mt][nt][2], acc[mt][nt][3]);
        }
}

// ---------------- prep ----------------
__global__ __launch_bounds__(256) void split_x_kernel(const float* __restrict__ x){
    int idx = blockIdx.x*256 + threadIdx.x;
    float v = x[idx];
    __nv_bfloat16 h = __float2bfloat16(v);
    g_xh[idx] = h;
    g_xl[idx] = __float2bfloat16(v - __bfloat162float(h));
}
__global__ __launch_bounds__(256) void wsplit_kernel(const float* __restrict__ W,
                                                     __nv_bfloat16* __restrict__ oh,
                                                     __nv_bfloat16* __restrict__ ol,
                                                     int K, int N){
    __shared__ float tl[32][33];
    const int n0 = blockIdx.x*32, k0 = blockIdx.y*32;
    const int tx = threadIdx.x & 31, ty = threadIdx.x >> 5;
    #pragma unroll
    for (int i = 0; i < 4; i++)
        tl[ty + i*8][tx] = W[(size_t)(k0 + ty + i*8)*N + n0 + tx];
    __syncthreads();
    #pragma unroll
    for (int i = 0; i < 4; i++){
        int nl = ty + i*8;
        float v = tl[tx][nl];
        __nv_bfloat16 h = __float2bfloat16(v);
        size_t o = (size_t)(n0 + nl)*K + k0 + tx;
        oh[o] = h;
        ol[o] = __float2bfloat16(v - __bfloat162float(h));
    }
}
__global__ __launch_bounds__(256) void wsplit_direct(const float* __restrict__ W,
                                                     __nv_bfloat16* __restrict__ oh,
                                                     __nv_bfloat16* __restrict__ ol,
                                                     int ldw, int coloff, int JCOLS){
    int idx = blockIdx.x*256 + threadIdx.x;
    int k = idx / JCOLS, j = idx - k*JCOLS;
    float v = W[(size_t)k*ldw + coloff + j];
    __nv_bfloat16 h = __float2bfloat16(v);
    oh[idx] = h;
    ol[idx] = __float2bfloat16(v - __bfloat162float(h));
}

// ---------------- conv + SiLU (per-batch) ----------------
__global__ __launch_bounds__(256) void conv_silu_kernel(const float* __restrict__ cw,
                                                        const float* __restrict__ cb,
                                                        int row0){
    int idx0 = blockIdx.x*256 + threadIdx.x;          // within one batch
    int d    = idx0 & (DINNER - 1);
    int row  = row0 + (idx0 >> 11);
    int t    = row & (LL - 1);
    size_t idx = (size_t)row*DINNER + d;
    float acc = cb[d];
    #pragma unroll
    for (int k = 0; k < DCONV; k++){
        int tt = t - (DCONV - 1) + k;
        if (tt >= 0)
            acc = fmaf(g_xz[(size_t)(row - (DCONV - 1) + k)*(2*DINNER) + d], cw[d*DCONV + k], acc);
    }
    float v = silu_f(acc);
    g_xc[idx] = v;
    __nv_bfloat16 h = __float2bfloat16(v);
    g_xch[idx] = h;
    g_xcl[idx] = __float2bfloat16(v - __bfloat162float(h));
}

// ---------------- scan (per-batch kernels) ----------------
__global__ __launch_bounds__(256) void scan_phase1(const float* __restrict__ A_log, int b){
    const int blk = blockIdx.x;
    const int dgrp = blk & 15, chunk = blk >> 4;
    const int tid = threadIdx.x, dloc = tid >> 1, half = tid & 1;
    const int d = dgrp*128 + dloc, s0 = half*32;
    const float u = -expf(A_log[d*DSTATE]) * LOG2E;
    float a2[32], h[32];
    bool fast = true;
    #pragma unroll
    for (int i = 0; i < 32; i++){
        a2[i] = -expf(A_log[d*DSTATE + s0 + i]) * LOG2E;
        float ex = u * (float)(s0 + i + 1);
        fast = fast && (fabsf(a2[i] - ex) <= 1e-6f*fabsf(ex) + 1e-30f);
        h[i] = 0.f;
    }
    __shared__ float sBC[2][128];
    const int rowbase = b*LL + chunk*CHUNK;
    float sdt = 0.f;
    for (int t = 0; t < CHUNK; t++){
        const int row = rowbase + t;
        if (tid < 128) sBC[t & 1][tid] = g_bc[(size_t)row*128 + tid];
        __syncthreads();
        const float dtv = g_dt[(size_t)row*DINNER + d];
        const float uv  = dtv * g_xc[(size_t)row*DINNER + d];
        const float* Bv = &sBC[t & 1][s0];
        sdt += dtv;
        if (fast){
            float q = ex2f(dtv * u);
            float q2=q*q, q4=q2*q2, q8=q4*q4, q16=q8*q8;
            float dA0;
            if (s0 == 0) dA0 = q;
            else { float q32=q16*q16; dA0 = q32*q; }
            float dA1 = dA0*q16;
            #pragma unroll
            for (int i = 0; i < 16; i++){
                h[i]    = fmaf(dA0, h[i],    uv * Bv[i]);
                h[i+16] = fmaf(dA1, h[i+16], uv * Bv[i+16]);
                dA0 *= q; dA1 *= q;
            }
        } else {
            #pragma unroll
            for (int i = 0; i < 32; i++){
                float dA = ex2f(dtv * a2[i]);
                h[i] = fmaf(dA, h[i], uv * Bv[i]);
            }
        }
    }
    float p[32];
    if (fast){
        float qp = ex2f(sdt * u);
        float p2=qp*qp, p4=p2*p2, p8=p4*p4, p16=p8*p8;
        float dP0;
        if (s0 == 0) dP0 = qp;
        else { float p32=p16*p16; dP0 = p32*qp; }
        float dP1 = dP0*p16;
        #pragma unroll
        for (int i = 0; i < 16; i++){
            p[i] = dP0; p[i+16] = dP1;
            dP0 *= qp; dP1 *= qp;
        }
    } else {
        #pragma unroll
        for (int i = 0; i < 32; i++) p[i] = ex2f(a2[i] * sdt);
    }
    const int base = ((b*NCHUNK + chunk)*DSTATE + s0)*DINNER + d;
    #pragma unroll
    for (int i = 0; i < 32; i++){ g_E[base + i*DINNER] = h[i]; g_P[base + i*DINNER] = p[i]; }
}
__global__ __launch_bounds__(256) void scan_combine(int b){
    const int idx = blockIdx.x*256 + threadIdx.x;
    const int d = idx & (DINNER-1), s = idx >> 11;
    float h = 0.f;
    for (int j = 0; j < NCHUNK; j++){
        const int o = ((b*NCHUNK + j)*DSTATE + s)*DINNER + d;
        g_hin[o] = h;
        h = fmaf(g_P[o], h, g_E[o]);
    }
}
__global__ __launch_bounds__(256) void scan_phase3(const float* __restrict__ A_log,
                                                   const float* __restrict__ D_param, int b){
    const int blk = blockIdx.x;
    const int dgrp = blk & 15, chunk = blk >> 4;
    const int tid = threadIdx.x, dloc = tid >> 1, half = tid & 1;
    const int d = dgrp*128 + dloc, s0 = half*32;
    const float u = -expf(A_log[d*DSTATE]) * LOG2E;
    float a2[32], h[32];
    bool fast = true;
    const int hbase = ((b*NCHUNK + chunk)*DSTATE + s0)*DINNER + d;
    #pragma unroll
    for (int i = 0; i < 32; i++){
        a2[i] = -expf(A_log[d*DSTATE + s0 + i]) * LOG2E;
        float ex = u * (float)(s0 + i + 1);
        fast = fast && (fabsf(a2[i] - ex) <= 1e-6f*fabsf(ex) + 1e-30f);
        h[i]  = g_hin[hbase + i*DINNER];
    }
    const float Dv = D_param[d];
    __shared__ float sBC[2][128];
    const int rowbase = b*LL + chunk*CHUNK;
    for (int t = 0; t < CHUNK; t++){
        const int row = rowbase + t;
        if (tid < 128) sBC[t & 1][tid] = g_bc[(size_t)row*128 + tid];
        __syncthreads();
        const float dtv = g_dt[(size_t)row*DINNER + d];
        const float xcv = g_xc[(size_t)row*DINNER + d];
        const float uv  = dtv * xcv;
        const float* Bv = &sBC[t & 1][s0];
        const float* Cv = &sBC[t & 1][64 + s0];
        float yacc = 0.f;
        if (fast){
            float q = ex2f(dtv * u);
            float q2=q*q, q4=q2*q2, q8=q4*q4, q16=q8*q8;
            float dA0;
            if (s0 == 0) dA0 = q;
            else { float q32=q16*q16; dA0 = q32*q; }
            float dA1 = dA0*q16;
            #pragma unroll
            for (int i = 0; i < 16; i++){
                h[i]    = fmaf(dA0, h[i],    uv * Bv[i]);
                yacc    = fmaf(h[i],    Cv[i],    yacc);
                h[i+16] = fmaf(dA1, h[i+16], uv * Bv[i+16]);
                yacc    = fmaf(h[i+16], Cv[i+16], yacc);
                dA0 *= q; dA1 *= q;
            }
        } else {
            #pragma unroll
            for (int i = 0; i < 32; i++){
                float dA = ex2f(dtv * a2[i]);
                h[i] = fmaf(dA, h[i], uv * Bv[i]);
                yacc = fmaf(h[i], Cv[i], yacc);
            }
        }
        yacc += __shfl_xor_sync(0xffffffffu, yacc, 1);
        if (half == 0){
            const size_t o = (size_t)row*DINNER + d;
            g_y[o] = yacc + Dv * xcv;
        }
    }
}

// ---------------- RMSNorm + silu(z) gate -> split bf16 ----------------
__global__ __launch_bounds__(256) void norm_kernel(const float* __restrict__ norm_w, int row0){
    const int row = row0 + blockIdx.x, tid = threadIdx.x;
    const size_t base = (size_t)row*DINNER;
    float ss = 0.f;
    for (int i = tid; i < DINNER; i += 256){
        float v = g_y[base + i];
        ss = fmaf(v, v, ss);
    }
    #pragma unroll
    for (int o = 16; o; o >>= 1) ss += __shfl_xor_sync(0xffffffffu, ss, o);
    __shared__ float red[8];
    __shared__ float s_inv;
    if ((tid & 31) == 0) red[tid >> 5] = ss;
    __syncthreads();
    if (tid == 0){
        float t = 0.f;
        #pragma unroll
        for (int i = 0; i < 8; i++) t += red[i];
        s_inv = rsqrtf(t/(float)DINNER + EPSV);
    }
    __syncthreads();
    const float inv = s_inv;
    for (int i = tid; i < DINNER; i += 256){
        float v  = g_y[base + i]*inv*norm_w[i];
        float zv = g_xz[(size_t)row*(2*DINNER) + DINNER + i];
        float yv = v*silu_f(zv);
        __nv_bfloat16 h = __float2bfloat16(yv);
        g_ynh[base + i] = h;
        g_ynl[base + i] = __float2bfloat16(yv - __bfloat162float(h));
    }
}

// ---------------- host-side tensormap builder (dlopen, no -lcuda) ----------
typedef CUresult (*EncFn)(CUtensorMap*, CUtensorMapDataType, cuuint32_t, void*,
    const cuuint64_t*, const cuuint64_t*, const cuuint32_t*, const cuuint32_t*,
    CUtensorMapInterleave, CUtensorMapSwizzle, CUtensorMapL2promotion, CUtensorMapFloatOOBfill);

static EncFn get_enc(){
    void* h = dlopen("libcuda.so.1", RTLD_LAZY | RTLD_GLOBAL);
    if (!h) h = dlopen("libcuda.so", RTLD_LAZY | RTLD_GLOBAL);
    if (!h) return nullptr;
    return (EncFn)dlsym(h, "cuTensorMapEncodeTiled");
}
static void mkmap(EncFn f, CUtensorMap* m, void* p, uint64_t K, uint64_t R, uint32_t boxR){
    if (!f || !p) return;
    cuuint64_t gd[2] = {K, R};
    cuuint64_t gs[1] = {K*2};
    cuuint32_t bd[2] = {64, boxR};
    cuuint32_t es[2] = {1, 1};
    f(m, CU_TENSOR_MAP_DATA_TYPE_BFLOAT16, 2, p, gd, gs, bd, es,
      CU_TENSOR_MAP_INTERLEAVE_NONE, CU_TENSOR_MAP_SWIZZLE_128B,
      CU_TENSOR_MAP_L2_PROMOTION_L2_128B, CU_TENSOR_MAP_FLOAT_OOB_FILL_NONE);
}

// ---------------- launch ----------------
extern "C" void kernel_launch(void* const* d_in, const int* in_sizes, int n_in,
                              void* d_out, int out_size){
    const float* x      = (const float*)d_in[0];
    const float* W_in   = (const float*)d_in[1];
    const float* conv_w = (const float*)d_in[2];
    const float* conv_b = (const float*)d_in[3];
    const float* W_x    = (const float*)d_in[4];
    const float* W_dt   = (const float*)d_in[5];
    const float* b_dt   = (const float*)d_in[6];
    const float* A_log  = (const float*)d_in[7];
    const float* D_par  = (const float*)d_in[8];
    const float* W_out  = (const float*)d_in[9];
    const float* norm_w = (const float*)d_in[10];
    float* out = (float*)d_out;

    const int STG256 = 32768 + 256*256;
    const int STG128 = 32768 + 128*256;
    const int SM256  = 2*STG256 + 1024 + 64;
    const int SM128  = 2*STG128 + 1024 + 64;
    cudaFuncSetAttribute(gemm1_tc,   cudaFuncAttributeMaxDynamicSharedMemorySize, SM256);
    cudaFuncSetAttribute(gemm2a_tc,  cudaFuncAttributeMaxDynamicSharedMemorySize, SM128);
    cudaFuncSetAttribute(wcombine_tc,cudaFuncAttributeMaxDynamicSharedMemorySize, SM256);
    cudaFuncSetAttribute(gemm3_tc,   cudaFuncAttributeMaxDynamicSharedMemorySize, SM256);
    cudaFuncSetAttribute(gemm4_tc,   cudaFuncAttributeMaxDynamicSharedMemorySize, SM256);

    void *xh,*xl,*xch,*xcl,*ynh,*ynl,*winh,*winl,*wxh,*wxl,*wdth,*wdtl,*wouth,*woutl,*wx2h,*wx2l,*wch,*wcl;
    cudaGetSymbolAddress(&xh,  g_xh);   cudaGetSymbolAddress(&xl,  g_xl);
    cudaGetSymbolAddress(&xch, g_xch);  cudaGetSymbolAddress(&xcl, g_xcl);
    cudaGetSymbolAddress(&ynh, g_ynh);  cudaGetSymbolAddress(&ynl, g_ynl);
    cudaGetSymbolAddress(&winh,g_winh); cudaGetSymbolAddress(&winl,g_winl);
    cudaGetSymbolAddress(&wxh, g_wxh);  cudaGetSymbolAddress(&wxl, g_wxl);
    cudaGetSymbolAddress(&wdth,g_wdth); cudaGetSymbolAddress(&wdtl,g_wdtl);
    cudaGetSymbolAddress(&wouth,g_wouth);cudaGetSymbolAddress(&woutl,g_woutl);
    cudaGetSymbolAddress(&wx2h,g_wx2h); cudaGetSymbolAddress(&wx2l,g_wx2l);
    cudaGetSymbolAddress(&wch, g_wch);  cudaGetSymbolAddress(&wcl, g_wcl);

    static EncFn enc = nullptr;
    if (!enc) enc = get_enc();
    static CUtensorMap m_xh, m_xl, m_xch, m_xcl, m_ynh, m_ynl;
    static CUtensorMap m_winh, m_winl, m_wxh, m_wxl, m_wdth, m_wdtl;
    static CUtensorMap m_wouth, m_woutl, m_wx2h, m_wx2l, m_wch, m_wcl;
    mkmap(enc, &m_xh,   xh,   1024, ROWS, 128);
    mkmap(enc, &m_xl,   xl,   1024, ROWS, 128);
    mkmap(enc, &m_xch,  xch,  2048, ROWS, 128);
    mkmap(enc, &m_xcl,  xcl,  2048, ROWS, 128);
    mkmap(enc, &m_ynh,  ynh,  2048, ROWS, 128);
    mkmap(enc, &m_ynl,  ynl,  2048, ROWS, 128);
    mkmap(enc, &m_winh, winh, 1024, 4096, 256);
    mkmap(enc, &m_winl, winl, 1024, 4096, 256);
    mkmap(enc, &m_wxh,  wxh,  2048, 128,  128);
    mkmap(enc, &m_wxl,  wxl,  2048, 128,  128);
    mkmap(enc, &m_wdth, wdth, 2048, 2048, 128);
    mkmap(enc, &m_wdtl, wdtl, 2048, 2048, 128);
    mkmap(enc, &m_wouth,wouth,2048, 1024, 256);
    mkmap(enc, &m_woutl,woutl,2048, 1024, 256);
    mkmap(enc, &m_wx2h, wx2h, 2048, 2048, 256);
    mkmap(enc, &m_wx2l, wx2l, 2048, 2048, 256);
    mkmap(enc, &m_wch,  wch,  2048, 2048, 256);
    mkmap(enc, &m_wcl,  wcl,  2048, 2048, 256);

    static cudaStream_t sB = nullptr, sC = nullptr;
    static cudaEvent_t evRoot, evX, evW, evG1a, evConv0, ev3a, evBC0, evDoneB, evDoneC;
    if (!sB){
        cudaStreamCreateWithFlags(&sB, cudaStreamNonBlocking);
        cudaStreamCreateWithFlags(&sC, cudaStreamNonBlocking);
        cudaEventCreateWithFlags(&evRoot, cudaEventDisableTiming);
        cudaEventCreateWithFlags(&evX,    cudaEventDisableTiming);
        cudaEventCreateWithFlags(&evW,    cudaEventDisableTiming);
        cudaEventCreateWithFlags(&evG1a,  cudaEventDisableTiming);
        cudaEventCreateWithFlags(&evConv0,cudaEventDisableTiming);
        cudaEventCreateWithFlags(&ev3a,   cudaEventDisableTiming);
        cudaEventCreateWithFlags(&evBC0,  cudaEventDisableTiming);
        cudaEventCreateWithFlags(&evDoneB,cudaEventDisableTiming);
        cudaEventCreateWithFlags(&evDoneC,cudaEventDisableTiming);
    }

    // ---- root fork ----
    split_x_kernel<<<(ROWS*DMODEL)/256, 256>>>(x);
    wsplit_kernel<<<dim3(4096/32, 1024/32), 256>>>(W_in, (__nv_bfloat16*)winh, (__nv_bfloat16*)winl, 1024, 4096);
    cudaEventRecord(evX, 0);

    // sC: weight prep + wcombine (overlaps gemm1(b0))
    cudaStreamWaitEvent(sC, evX, 0);
    wsplit_kernel<<<dim3(128/32,  2048/32), 256, 0, sC>>>(W_x,   (__nv_bfloat16*)wxh,  (__nv_bfloat16*)wxl,  2048, 2176);
    wsplit_kernel<<<dim3(2048/32, 2048/32), 256, 0, sC>>>(W_dt,  (__nv_bfloat16*)wdth, (__nv_bfloat16*)wdtl, 2048, 2048);
    wsplit_kernel<<<dim3(1024/32, 2048/32), 256, 0, sC>>>(W_out, (__nv_bfloat16*)wouth,(__nv_bfloat16*)woutl,2048, 1024);
    wsplit_direct<<<(2048*2048)/256, 256, 0, sC>>>(W_x, (__nv_bfloat16*)wx2h, (__nv_bfloat16*)wx2l, 2176, 128, 2048);
    wcombine_tc<<<dim3(8, 16), 512, SM256, sC>>>(m_wdth, m_wdtl, m_wx2h, m_wx2l);
    cudaEventRecord(evW, sC);

    // s0: gemm1(b0)
    gemm1_tc<<<dim3(16, 32), 512, SM256>>>(m_xh, m_xl, m_winh, m_winl, 0);
    cudaEventRecord(evG1a, 0);

    // sB: gemm1(b1) + conv(b1)  (overlaps b0 conv/gemm3 chain)
    cudaStreamWaitEvent(sB, evG1a, 0);
    gemm1_tc<<<dim3(16, 32), 512, SM256, sB>>>(m_xh, m_xl, m_winh, m_winl, LL);
    conv_silu_kernel<<<(LL*DINNER)/256, 256, 0, sB>>>(conv_w, conv_b, LL);

    // s0: conv(b0)
    conv_silu_kernel<<<(LL*DINNER)/256, 256>>>(conv_w, conv_b, 0);
    cudaEventRecord(evConv0, 0);

    // sC: gemm2a(b0) concurrent with gemm3(b0)   (sC already did wcombine -> has weights)
    cudaStreamWaitEvent(sC, evConv0, 0);
    gemm2a_tc<<<dim3(1, 32), 512, SM128, sC>>>(m_xch, m_xcl, m_wxh, m_wxl, 0);
    cudaEventRecord(evBC0, sC);

    // s0: gemm3(b0) then b0 scan chain
    cudaStreamWaitEvent(0, evW, 0);
    gemm3_tc<<<dim3(8, 32), 512, SM256>>>(m_xch, m_xcl, m_wch, m_wcl, b_dt, 0);
    cudaEventRecord(ev3a, 0);
    cudaStreamWaitEvent(0, evBC0, 0);
    scan_phase1<<<NCHUNK*(DINNER/128), 256>>>(A_log, 0);
    scan_combine<<<(DSTATE*DINNER)/256, 256>>>(0);
    scan_phase3<<<NCHUNK*(DINNER/128), 256>>>(A_log, D_par, 0);
    norm_kernel<<<LL, 256>>>(norm_w, 0);
    gemm4_tc<<<dim3(4, 32), 512, SM256>>>(m_ynh, m_ynl, m_wouth, m_woutl, out, 0);

    // sB: b1 chain (gemm2a + gemm3 ordered after gemm3(b0) to give b0 priority)
    cudaStreamWaitEvent(sB, evW, 0);
    gemm2a_tc<<<dim3(1, 32), 512, SM128, sB>>>(m_xch, m_xcl, m_wxh, m_wxl, LL);
    cudaStreamWaitEvent(sB, ev3a, 0);
    gemm3_tc<<<dim3(8, 32), 512, SM256, sB>>>(m_xch, m_xcl, m_wch, m_wcl, b_dt, LL);
    scan_phase1<<<NCHUNK*(DINNER/128), 256, 0, sB>>>(A_log, 1);
    scan_combine<<<(DSTATE*DINNER)/256, 256, 0, sB>>>(1);
    scan_phase3<<<NCHUNK*(DINNER/128), 256, 0, sB>>>(A_log, D_par, 1);
    norm_kernel<<<LL, 256, 0, sB>>>(norm_w, LL);
    gemm4_tc<<<dim3(4, 32), 512, SM256, sB>>>(m_ynh, m_ynl, m_wouth, m_woutl, out, LL);
    cudaEventRecord(evDoneB, sB);

    // join all side streams into s0
    cudaEventRecord(evDoneC, sC);
    cudaStreamWaitEvent(0, evDoneB, 0);
    cudaStreamWaitEvent(0, evDoneC, 0);
}